// round 1
// baseline (speedup 1.0000x reference)
#include <cuda_runtime.h>
#include <math.h>

// Problem constants
#define B_   64
#define T_   90
#define O_   5
#define D_   256
#define H_   256
#define EA_  4096
#define R_   5
#define NB_  8
#define NPG_ 95
#define TO_  (T_*O_)        // 450
#define TT_  (T_*T_)        // 8100
#define RH_  (R_*H_)        // 1280
#define S_ELEMS ((size_t)B_*R_*NPG_*T_)   // 2,736,000
#define XW_ELEMS ((size_t)B_*R_*T_*H_)    // 7,372,800

// Scratch (device globals; no allocation allowed)
__device__ float g_W [R_*D_*H_];    // combined basis weights [R,D,H]
__device__ float g_sm[B_*TT_];      // softmaxed scores sm[b,t,s]
__device__ float g_S [B_*R_*NPG_*T_]; // per-(b,r) aggregation matrix [NPG,T]
__device__ float g_XW[B_*R_*T_*H_];   // XW[b,r] = X_b[0:T] @ W[r]

// ---------------------------------------------------------------------------
// K1: W[r,d,h] = sum_n comp[r,n] * bases[n,d,h]
// ---------------------------------------------------------------------------
__global__ void k_combine(const float* __restrict__ bases,
                          const float* __restrict__ comp) {
    int dh = blockIdx.x * blockDim.x + threadIdx.x;
    if (dh >= D_*H_) return;
    float v[NB_];
#pragma unroll
    for (int n = 0; n < NB_; n++) v[n] = bases[(size_t)n*D_*H_ + dh];
#pragma unroll
    for (int r = 0; r < R_; r++) {
        float acc = 0.f;
#pragma unroll
        for (int n = 0; n < NB_; n++) acc += __ldg(&comp[r*NB_ + n]) * v[n];
        g_W[(size_t)r*D_*H_ + dh] = acc;
    }
}

// ---------------------------------------------------------------------------
// K2: scale[b] = M_b (90x256) @ Ws^T (256x90), then column softmax over t.
// One block per batch. sm[b,t,s] = exp(scale[b,t,s]-max_t)/sum_t
// ---------------------------------------------------------------------------
__global__ void k_scale_softmax(const float* __restrict__ M,
                                const float* __restrict__ Ws) {
    int b = blockIdx.x;
    __shared__ float As[96][17];
    __shared__ float Bs[96][17];
    __shared__ float Cs[TT_];          // 32.4 KB
    int tid = threadIdx.x;
    int ty = tid >> 4, tx = tid & 15;
    float acc[6][6] = {};
    const float* Mb = M + (size_t)b*T_*D_;

    for (int k0 = 0; k0 < D_; k0 += 16) {
        for (int i = tid; i < 96*16; i += 256) {
            int r = i >> 4, c = i & 15;
            As[r][c] = (r < T_) ? Mb[(size_t)r*D_ + k0 + c] : 0.f;
            Bs[r][c] = (r < T_) ? Ws[(size_t)r*D_ + k0 + c] : 0.f;
        }
        __syncthreads();
#pragma unroll
        for (int kk = 0; kk < 16; kk++) {
            float a[6], bb[6];
#pragma unroll
            for (int i = 0; i < 6; i++) a[i]  = As[ty*6+i][kk];
#pragma unroll
            for (int j = 0; j < 6; j++) bb[j] = Bs[tx*6+j][kk];
#pragma unroll
            for (int i = 0; i < 6; i++)
#pragma unroll
                for (int j = 0; j < 6; j++) acc[i][j] += a[i]*bb[j];
        }
        __syncthreads();
    }
    // stash C[t][s] into smem
#pragma unroll
    for (int i = 0; i < 6; i++) {
        int t = ty*6 + i; if (t >= T_) continue;
#pragma unroll
        for (int j = 0; j < 6; j++) {
            int s = tx*6 + j; if (s >= T_) continue;
            Cs[t*T_ + s] = acc[i][j];
        }
    }
    __syncthreads();
    // column softmax (over t) for column s = tid
    if (tid < T_) {
        int s = tid;
        float mx = -1e30f;
        for (int t = 0; t < T_; t++) mx = fmaxf(mx, Cs[t*T_ + s]);
        float sum = 0.f;
        for (int t = 0; t < T_; t++) {
            float e = expf(Cs[t*T_ + s] - mx);
            Cs[t*T_ + s] = e;
            sum += e;
        }
        float inv = 1.f / sum;
        for (int t = 0; t < T_; t++)
            g_sm[(size_t)b*TT_ + t*T_ + s] = Cs[t*T_ + s] * inv;
    }
}

// ---------------------------------------------------------------------------
// K3: zero S
// ---------------------------------------------------------------------------
__global__ void k_zero_s() {
    size_t i = (size_t)blockIdx.x * blockDim.x + threadIdx.x;
    size_t stride = (size_t)gridDim.x * blockDim.x;
    for (; i < S_ELEMS; i += stride) g_S[i] = 0.f;
}

// ---------------------------------------------------------------------------
// K4: scatter edges into S.
//   attention edges: S[b, r, dst, src] += sm[b, dst, src]
//   tag edges:       S[b, R-1, T+o, t] += node_att[b, t, o]
// ---------------------------------------------------------------------------
__global__ void k_scatter(const int*   __restrict__ esrc,
                          const int*   __restrict__ edst,
                          const int*   __restrict__ etype,
                          const float* __restrict__ node_att) {
    int i = blockIdx.x * blockDim.x + threadIdx.x;
    const int Eatt = B_*EA_;
    if (i < Eatt) {
        int b = i / EA_;
        int s = esrc[i], d = edst[i], r = etype[i];
        float norm = g_sm[(size_t)b*TT_ + d*T_ + s];
        atomicAdd(&g_S[(((size_t)b*R_ + r)*NPG_ + d)*T_ + s], norm);
    } else {
        int j = i - Eatt;
        if (j < B_*TO_) {
            int b   = j / TO_;
            int rem = j - b*TO_;
            int t = rem / O_, o = rem - t*O_;
            atomicAdd(&g_S[(((size_t)b*R_ + (R_-1))*NPG_ + (T_+o))*T_ + t],
                      node_att[j]);
        }
    }
}

// ---------------------------------------------------------------------------
// K5: XW[b,r] = X_b[0:T, :] @ W[r]   (batched, grid = (RH/64, B))
//   BM=96 (covers T=90), BN=64, BK=16, 256 threads, 6x4 per thread
// ---------------------------------------------------------------------------
__global__ void k_xw(const float* __restrict__ x) {
    int b  = blockIdx.y;
    int n0 = blockIdx.x * 64;          // column in [0, R*H)
    int r  = n0 / H_;                  // tile stays within one relation
    int h0 = n0 - r*H_;
    __shared__ float  As[96][17];
    __shared__ float4 Bs[16][16];
    int tid = threadIdx.x;
    int ty = tid >> 4, tx = tid & 15;
    float acc[6][4] = {};
    const float* xb = x + (size_t)b*NPG_*D_;
    const float* Wr = g_W + (size_t)r*D_*H_ + h0;

    for (int k0 = 0; k0 < D_; k0 += 16) {
        for (int i = tid; i < 96*16; i += 256) {
            int rr = i >> 4, c = i & 15;
            As[rr][c] = (rr < T_) ? xb[(size_t)rr*D_ + k0 + c] : 0.f;
        }
        {
            int krow = tid >> 4;   // 0..15
            int nc4  = tid & 15;   // 0..15
            Bs[krow][nc4] = *(const float4*)(Wr + (size_t)(k0 + krow)*H_ + nc4*4);
        }
        __syncthreads();
#pragma unroll
        for (int kk = 0; kk < 16; kk++) {
            float a[6];
#pragma unroll
            for (int i = 0; i < 6; i++) a[i] = As[ty*6+i][kk];
            float4 bv = Bs[kk][tx];
            float bb[4] = {bv.x, bv.y, bv.z, bv.w};
#pragma unroll
            for (int i = 0; i < 6; i++)
#pragma unroll
                for (int j = 0; j < 4; j++) acc[i][j] += a[i]*bb[j];
        }
        __syncthreads();
    }
    float* out = g_XW + (size_t)(b*R_ + r)*T_*H_;
#pragma unroll
    for (int i = 0; i < 6; i++) {
        int t = ty*6 + i; if (t >= T_) continue;
        float4 v = make_float4(acc[i][0], acc[i][1], acc[i][2], acc[i][3]);
        *(float4*)(out + (size_t)t*H_ + h0 + tx*4) = v;
    }
}

// ---------------------------------------------------------------------------
// K6: out[b] = S_cat[b] (95 x 450) @ XW_stack[b] (450 x 256)
//            + x_b (95 x 256) @ root (256 x 256) + bias
//   grid = (H/64, B), BM=96, BN=64, 256 threads, 6x4 per thread
// ---------------------------------------------------------------------------
__global__ void k_out(const float* __restrict__ x,
                      const float* __restrict__ root,
                      const float* __restrict__ bias,
                      float* __restrict__ out) {
    int b  = blockIdx.y;
    int h0 = blockIdx.x * 64;
    __shared__ float As[96][19];
    __shared__ float Bs[18][64];
    int tid = threadIdx.x;
    int ty = tid >> 4, tx = tid & 15;
    float acc[6][4] = {};

    // Phase 1: sum over r, s (K = R*T = 450, chunks of 18)
    for (int r = 0; r < R_; r++) {
        const float* Sb  = g_S  + (size_t)(b*R_ + r)*NPG_*T_;
        const float* XWb = g_XW + (size_t)(b*R_ + r)*T_*H_ + h0;
        for (int s0 = 0; s0 < T_; s0 += 18) {
            for (int i = tid; i < 96*18; i += 256) {
                int rr = i / 18, c = i - rr*18;
                As[rr][c] = (rr < NPG_) ? Sb[(size_t)rr*T_ + s0 + c] : 0.f;
            }
            for (int i = tid; i < 18*64; i += 256) {
                int kk = i >> 6, c = i & 63;
                Bs[kk][c] = XWb[(size_t)(s0 + kk)*H_ + c];
            }
            __syncthreads();
#pragma unroll
            for (int kk = 0; kk < 18; kk++) {
                float a[6], bb[4];
#pragma unroll
                for (int i = 0; i < 6; i++) a[i]  = As[ty*6+i][kk];
#pragma unroll
                for (int j = 0; j < 4; j++) bb[j] = Bs[kk][tx*4+j];
#pragma unroll
                for (int i = 0; i < 6; i++)
#pragma unroll
                    for (int j = 0; j < 4; j++) acc[i][j] += a[i]*bb[j];
            }
            __syncthreads();
        }
    }

    // Phase 2: + x_b @ root (K = D = 256, chunks of 16)
    const float* xb = x + (size_t)b*NPG_*D_;
    for (int k0 = 0; k0 < D_; k0 += 16) {
        for (int i = tid; i < 96*16; i += 256) {
            int rr = i >> 4, c = i & 15;
            As[rr][c] = (rr < NPG_) ? xb[(size_t)rr*D_ + k0 + c] : 0.f;
        }
        for (int i = tid; i < 16*64; i += 256) {
            int kk = i >> 6, c = i & 63;
            Bs[kk][c] = root[(size_t)(k0 + kk)*H_ + h0 + c];
        }
        __syncthreads();
#pragma unroll
        for (int kk = 0; kk < 16; kk++) {
            float a[6], bb[4];
#pragma unroll
            for (int i = 0; i < 6; i++) a[i]  = As[ty*6+i][kk];
#pragma unroll
            for (int j = 0; j < 4; j++) bb[j] = Bs[kk][tx*4+j];
#pragma unroll
            for (int i = 0; i < 6; i++)
#pragma unroll
                for (int j = 0; j < 4; j++) acc[i][j] += a[i]*bb[j];
        }
        __syncthreads();
    }

    // Epilogue: + bias, write out
#pragma unroll
    for (int i = 0; i < 6; i++) {
        int row = ty*6 + i; if (row >= NPG_) continue;
#pragma unroll
        for (int j = 0; j < 4; j++) {
            int h = h0 + tx*4 + j;
            out[((size_t)b*NPG_ + row)*H_ + h] = acc[i][j] + bias[h];
        }
    }
}

// ---------------------------------------------------------------------------
// launch
// ---------------------------------------------------------------------------
extern "C" void kernel_launch(void* const* d_in, const int* in_sizes, int n_in,
                              void* d_out, int out_size) {
    const float* M        = (const float*)d_in[0];
    const float* x        = (const float*)d_in[1];
    const float* node_att = (const float*)d_in[2];
    const float* Ws       = (const float*)d_in[3];
    const float* bases    = (const float*)d_in[4];
    const float* comp     = (const float*)d_in[5];
    const float* root     = (const float*)d_in[6];
    const float* bias     = (const float*)d_in[7];
    const int*   esrc     = (const int*)d_in[8];
    const int*   edst     = (const int*)d_in[9];
    const int*   etype    = (const int*)d_in[10];
    float* out = (float*)d_out;

    k_combine<<<(D_*H_ + 255)/256, 256>>>(bases, comp);
    k_scale_softmax<<<B_, 256>>>(M, Ws);
    k_zero_s<<<2048, 256>>>();
    {
        int total = B_*EA_ + B_*TO_;
        k_scatter<<<(total + 255)/256, 256>>>(esrc, edst, etype, node_att);
    }
    k_xw<<<dim3(RH_/64, B_), 256>>>(x);
    k_out<<<dim3(H_/64, B_), 256>>>(x, root, bias, out);
}

// round 2
// speedup vs baseline: 1.3970x; 1.3970x over previous
#include <cuda_runtime.h>
#include <math.h>
#include <stdint.h>

// Problem constants
#define B_   64
#define T_   90
#define O_   5
#define D_   256
#define H_   256
#define EA_  4096
#define R_   5
#define NB_  8
#define NPG_ 95
#define TO_  (T_*O_)        // 450
#define TT_  (T_*T_)        // 8100
#define RH_  (R_*H_)        // 1280
#define S_ELEMS ((size_t)B_*R_*NPG_*T_)   // 2,736,000

// Scratch (device globals; no allocation allowed)
__device__ float g_W [R_*D_*H_];      // combined basis weights [R,D,H]
__device__ float g_sm[B_*TT_];        // softmaxed scores sm[b,t,s]
__device__ float g_S [B_*R_*NPG_*T_]; // per-(b,r) aggregation matrix [NPG,T]
__device__ float g_XW[(size_t)B_*R_*T_*H_]; // XW[b,r] = X_b[0:T] @ W[r]

// ---------------------------------------------------------------------------
// tf32 mma.sync helpers
// ---------------------------------------------------------------------------
__device__ __forceinline__ float to_tf32(float x) {
    uint32_t u;
    asm("cvt.rna.tf32.f32 %0, %1;" : "=r"(u) : "f"(x));
    return __uint_as_float(u);
}

__device__ __forceinline__ void mma_tf32(float c[4], const float4& a, const float2& b) {
    asm volatile(
        "mma.sync.aligned.m16n8k8.row.col.f32.tf32.tf32.f32 "
        "{%0,%1,%2,%3},{%4,%5,%6,%7},{%8,%9},{%0,%1,%2,%3};"
        : "+f"(c[0]), "+f"(c[1]), "+f"(c[2]), "+f"(c[3])
        : "r"(__float_as_uint(a.x)), "r"(__float_as_uint(a.y)),
          "r"(__float_as_uint(a.z)), "r"(__float_as_uint(a.w)),
          "r"(__float_as_uint(b.x)), "r"(__float_as_uint(b.y)));
}

// ---------------------------------------------------------------------------
// One BM=96 x BN=64 x BK=32 chunk, 256 threads (8 warps, 2x4 warp grid).
// sA: fragment-packed A  [mtile(6)][kstep(4)][lane(32)][reg(4)]  (12 KB)
// sB: fragment-packed B  [ntile(8)][kstep(4)][lane(32)][reg(2)]  ( 8 KB)
// A global is row-major (m x k), B global is row-major (k x n).
// ---------------------------------------------------------------------------
__device__ __forceinline__ void gemm_chunk32(
    const float* __restrict__ Ag, int lda, int mvalid, int kvalid,
    const float* __restrict__ Bg, int ldb,
    float* sA, float* sB, float acc[3][2][4])
{
    int tid = threadIdx.x;
    __syncthreads();   // protect previous chunk's smem from overwrite
    // ---- load + swizzle A (96 x 32) ----
#pragma unroll
    for (int t = 0; t < 3; t++) {
        int idx = tid + t * 256;
        int m = idx >> 3, k4 = (idx & 7) << 2;
        float v[4];
#pragma unroll
        for (int c = 0; c < 4; c++) {
            int k = k4 + c;
            v[c] = (m < mvalid && k < kvalid) ? Ag[(size_t)m * lda + k] : 0.f;
        }
#pragma unroll
        for (int c = 0; c < 4; c++) {
            int k = k4 + c;
            int off = ((m >> 4) * 4 + (k >> 3)) * 128
                    + ((((m & 7) << 2) | (k & 3)) << 2)
                    + (((m >> 3) & 1) | (((k >> 2) & 1) << 1));
            sA[off] = to_tf32(v[c]);
        }
    }
    // ---- load + swizzle B (32 x 64) ----
#pragma unroll
    for (int t = 0; t < 2; t++) {
        int idx = tid + t * 256;
        int k = idx >> 4, n4 = (idx & 15) << 2;
        float4 v;
        if (k < kvalid) v = *(const float4*)(Bg + (size_t)k * ldb + n4);
        else            v = make_float4(0.f, 0.f, 0.f, 0.f);
        float vv[4] = {v.x, v.y, v.z, v.w};
#pragma unroll
        for (int c = 0; c < 4; c++) {
            int n = n4 + c;
            int off = ((n >> 3) * 4 + (k >> 3)) * 64
                    + ((((n & 7) << 2) | (k & 3)) << 1)
                    + ((k >> 2) & 1);
            sB[off] = to_tf32(vv[c]);
        }
    }
    __syncthreads();
    // ---- mma mainloop ----
    int lane = tid & 31, wid = tid >> 5;
    int wm = wid >> 2, wn = wid & 3;
#pragma unroll
    for (int ks = 0; ks < 4; ks++) {
        float2 bfrag[2];
#pragma unroll
        for (int nt = 0; nt < 2; nt++) {
            int gnt = wn * 2 + nt;
            bfrag[nt] = *(const float2*)(sB + ((gnt * 4 + ks) * 32 + lane) * 2);
        }
#pragma unroll
        for (int mt = 0; mt < 3; mt++) {
            int gmt = wm * 3 + mt;
            float4 afrag = *(const float4*)(sA + ((gmt * 4 + ks) * 32 + lane) * 4);
#pragma unroll
            for (int nt = 0; nt < 2; nt++) mma_tf32(acc[mt][nt], afrag, bfrag[nt]);
        }
    }
}

// ---------------------------------------------------------------------------
// K1: W[r,d,h] = sum_n comp[r,n] * bases[n,d,h]
// ---------------------------------------------------------------------------
__global__ void k_combine(const float* __restrict__ bases,
                          const float* __restrict__ comp) {
    int dh = blockIdx.x * blockDim.x + threadIdx.x;
    if (dh >= D_*H_) return;
    float v[NB_];
#pragma unroll
    for (int n = 0; n < NB_; n++) v[n] = bases[(size_t)n*D_*H_ + dh];
#pragma unroll
    for (int r = 0; r < R_; r++) {
        float acc = 0.f;
#pragma unroll
        for (int n = 0; n < NB_; n++) acc += __ldg(&comp[r*NB_ + n]) * v[n];
        g_W[(size_t)r*D_*H_ + dh] = acc;
    }
}

// ---------------------------------------------------------------------------
// K2: scale[b] = M_b (90x256) @ Ws^T (256x90), then column softmax over t.
// (kept fp32 — feeds exp(); tf32 error here would amplify)
// ---------------------------------------------------------------------------
__global__ void k_scale_softmax(const float* __restrict__ M,
                                const float* __restrict__ Ws) {
    int b = blockIdx.x;
    __shared__ float As[96][17];
    __shared__ float Bs[96][17];
    __shared__ float Cs[TT_];
    int tid = threadIdx.x;
    int ty = tid >> 4, tx = tid & 15;
    float acc[6][6] = {};
    const float* Mb = M + (size_t)b*T_*D_;

    for (int k0 = 0; k0 < D_; k0 += 16) {
        for (int i = tid; i < 96*16; i += 256) {
            int r = i >> 4, c = i & 15;
            As[r][c] = (r < T_) ? Mb[(size_t)r*D_ + k0 + c] : 0.f;
            Bs[r][c] = (r < T_) ? Ws[(size_t)r*D_ + k0 + c] : 0.f;
        }
        __syncthreads();
#pragma unroll
        for (int kk = 0; kk < 16; kk++) {
            float a[6], bb[6];
#pragma unroll
            for (int i = 0; i < 6; i++) a[i]  = As[ty*6+i][kk];
#pragma unroll
            for (int j = 0; j < 6; j++) bb[j] = Bs[tx*6+j][kk];
#pragma unroll
            for (int i = 0; i < 6; i++)
#pragma unroll
                for (int j = 0; j < 6; j++) acc[i][j] += a[i]*bb[j];
        }
        __syncthreads();
    }
#pragma unroll
    for (int i = 0; i < 6; i++) {
        int t = ty*6 + i; if (t >= T_) continue;
#pragma unroll
        for (int j = 0; j < 6; j++) {
            int s = tx*6 + j; if (s >= T_) continue;
            Cs[t*T_ + s] = acc[i][j];
        }
    }
    __syncthreads();
    if (tid < T_) {
        int s = tid;
        float mx = -1e30f;
        for (int t = 0; t < T_; t++) mx = fmaxf(mx, Cs[t*T_ + s]);
        float sum = 0.f;
        for (int t = 0; t < T_; t++) {
            float e = expf(Cs[t*T_ + s] - mx);
            Cs[t*T_ + s] = e;
            sum += e;
        }
        float inv = 1.f / sum;
        for (int t = 0; t < T_; t++)
            g_sm[(size_t)b*TT_ + t*T_ + s] = Cs[t*T_ + s] * inv;
    }
}

// ---------------------------------------------------------------------------
// K3: zero S
// ---------------------------------------------------------------------------
__global__ void k_zero_s() {
    size_t i = (size_t)blockIdx.x * blockDim.x + threadIdx.x;
    size_t stride = (size_t)gridDim.x * blockDim.x;
    for (; i < S_ELEMS; i += stride) g_S[i] = 0.f;
}

// ---------------------------------------------------------------------------
// K4: scatter edges into S.
// ---------------------------------------------------------------------------
__global__ void k_scatter(const int*   __restrict__ esrc,
                          const int*   __restrict__ edst,
                          const int*   __restrict__ etype,
                          const float* __restrict__ node_att) {
    int i = blockIdx.x * blockDim.x + threadIdx.x;
    const int Eatt = B_*EA_;
    if (i < Eatt) {
        int b = i / EA_;
        int s = esrc[i], d = edst[i], r = etype[i];
        float norm = g_sm[(size_t)b*TT_ + d*T_ + s];
        atomicAdd(&g_S[(((size_t)b*R_ + r)*NPG_ + d)*T_ + s], norm);
    } else {
        int j = i - Eatt;
        if (j < B_*TO_) {
            int b   = j / TO_;
            int rem = j - b*TO_;
            int t = rem / O_, o = rem - t*O_;
            atomicAdd(&g_S[(((size_t)b*R_ + (R_-1))*NPG_ + (T_+o))*T_ + t],
                      node_att[j]);
        }
    }
}

// ---------------------------------------------------------------------------
// K5 (tf32 mma): XW[b,r] = X_b[0:T] @ W[r]
//   grid = (RH/64, B), 256 threads, BM=96 BN=64 BK=32
// ---------------------------------------------------------------------------
__global__ void __launch_bounds__(256)
k_xw_mma(const float* __restrict__ x) {
    __shared__ __align__(16) float sA[6*4*32*4];   // 12 KB
    __shared__ __align__(16) float sB[8*4*32*2];   //  8 KB
    int b  = blockIdx.y;
    int n0 = blockIdx.x * 64;
    int r  = n0 / H_;
    int h0 = n0 - r*H_;
    const float* xb = x + (size_t)b*NPG_*D_;
    const float* Wr = g_W + (size_t)r*D_*H_ + h0;

    float acc[3][2][4] = {};
    for (int k0 = 0; k0 < D_; k0 += 32)
        gemm_chunk32(xb + k0, D_, T_, 32, Wr + (size_t)k0*H_, H_, sA, sB, acc);

    int tid = threadIdx.x, lane = tid & 31, wid = tid >> 5;
    int wm = wid >> 2, wn = wid & 3;
    float* o = g_XW + (size_t)(b*R_ + r)*T_*H_;
#pragma unroll
    for (int mt = 0; mt < 3; mt++) {
#pragma unroll
        for (int nt = 0; nt < 2; nt++) {
            int row = wm*48 + mt*16 + (lane >> 2);
            int col = h0 + wn*16 + nt*8 + ((lane & 3) << 1);
            if (row < T_)
                *(float2*)(o + (size_t)row*H_ + col) =
                    make_float2(acc[mt][nt][0], acc[mt][nt][1]);
            if (row + 8 < T_)
                *(float2*)(o + (size_t)(row+8)*H_ + col) =
                    make_float2(acc[mt][nt][2], acc[mt][nt][3]);
        }
    }
}

// ---------------------------------------------------------------------------
// K6 (tf32 mma): out[b] = sum_r S_r[b] @ XW[b,r] + x_b @ root + bias
//   grid = (H/64, B), 256 threads
// ---------------------------------------------------------------------------
__global__ void __launch_bounds__(256)
k_out_mma(const float* __restrict__ x,
          const float* __restrict__ root,
          const float* __restrict__ bias,
          float* __restrict__ out) {
    __shared__ __align__(16) float sA[6*4*32*4];
    __shared__ __align__(16) float sB[8*4*32*2];
    int b  = blockIdx.y;
    int h0 = blockIdx.x * 64;

    float acc[3][2][4] = {};

    // Phase 1: sum over relations; K per r = 90, padded in 32-chunks
    for (int r = 0; r < R_; r++) {
        const float* Sb  = g_S  + (size_t)(b*R_ + r)*NPG_*T_;
        const float* XWb = g_XW + (size_t)(b*R_ + r)*T_*H_ + h0;
#pragma unroll
        for (int c = 0; c < 3; c++) {
            int s0 = c * 32;
            int kv = (T_ - s0) < 32 ? (T_ - s0) : 32;
            gemm_chunk32(Sb + s0, T_, NPG_, kv,
                         XWb + (size_t)s0*H_, H_, sA, sB, acc);
        }
    }
    // Phase 2: + x_b @ root
    const float* xb = x + (size_t)b*NPG_*D_;
    for (int k0 = 0; k0 < D_; k0 += 32)
        gemm_chunk32(xb + k0, D_, NPG_, 32,
                     root + (size_t)k0*H_ + h0, H_, sA, sB, acc);

    int tid = threadIdx.x, lane = tid & 31, wid = tid >> 5;
    int wm = wid >> 2, wn = wid & 3;
#pragma unroll
    for (int mt = 0; mt < 3; mt++) {
#pragma unroll
        for (int nt = 0; nt < 2; nt++) {
            int row = wm*48 + mt*16 + (lane >> 2);
            int col = h0 + wn*16 + nt*8 + ((lane & 3) << 1);
            if (row < NPG_) {
                float* p = out + ((size_t)b*NPG_ + row)*H_ + col;
                p[0] = acc[mt][nt][0] + bias[col];
                p[1] = acc[mt][nt][1] + bias[col+1];
            }
            if (row + 8 < NPG_) {
                float* p = out + ((size_t)b*NPG_ + row + 8)*H_ + col;
                p[0] = acc[mt][nt][2] + bias[col];
                p[1] = acc[mt][nt][3] + bias[col+1];
            }
        }
    }
}

// ---------------------------------------------------------------------------
// launch
// ---------------------------------------------------------------------------
extern "C" void kernel_launch(void* const* d_in, const int* in_sizes, int n_in,
                              void* d_out, int out_size) {
    const float* M        = (const float*)d_in[0];
    const float* x        = (const float*)d_in[1];
    const float* node_att = (const float*)d_in[2];
    const float* Ws       = (const float*)d_in[3];
    const float* bases    = (const float*)d_in[4];
    const float* comp     = (const float*)d_in[5];
    const float* root     = (const float*)d_in[6];
    const float* bias     = (const float*)d_in[7];
    const int*   esrc     = (const int*)d_in[8];
    const int*   edst     = (const int*)d_in[9];
    const int*   etype    = (const int*)d_in[10];
    float* out = (float*)d_out;

    k_combine<<<(D_*H_ + 255)/256, 256>>>(bases, comp);
    k_scale_softmax<<<B_, 256>>>(M, Ws);
    k_zero_s<<<2048, 256>>>();
    {
        int total = B_*EA_ + B_*TO_;
        k_scatter<<<(total + 255)/256, 256>>>(esrc, edst, etype, node_att);
    }
    k_xw_mma<<<dim3(RH_/64, B_), 256>>>(x);
    k_out_mma<<<dim3(H_/64, B_), 256>>>(x, root, bias, out);
}

// round 8
// speedup vs baseline: 2.1869x; 1.5654x over previous
#include <cuda_runtime.h>
#include <cuda_fp16.h>
#include <math.h>
#include <stdint.h>

// Problem constants
#define B_   64
#define T_   90
#define O_   5
#define D_   256
#define H_   256
#define EA_  4096
#define R_   5
#define NB_  8
#define NPG_ 95
#define TO_  (T_*O_)        // 450
#define TT_  (T_*T_)        // 8100
#define S_ELEMS ((size_t)B_*R_*NPG_*T_)

// Scratch (device globals; no allocation allowed)
__device__ float g_W [R_*D_*H_];      // combined basis weights [R,D,H]
__device__ float g_sm[B_*TT_];        // softmaxed scores sm[b,t,s]
__device__ float g_S [B_*R_*NPG_*T_]; // per-(b,r) aggregation matrix [NPG,T]
__device__ float g_XW[(size_t)B_*R_*T_*H_]; // XW[b,r] = X_b[0:T] @ W[r]

// ---------------------------------------------------------------------------
// fp16 mma.sync m16n8k16 (f32 accumulate)
// ---------------------------------------------------------------------------
__device__ __forceinline__ void mma_fp16(float c[4], const uint4& a, const uint2& b) {
    asm volatile(
        "mma.sync.aligned.m16n8k16.row.col.f32.f16.f16.f32 "
        "{%0,%1,%2,%3},{%4,%5,%6,%7},{%8,%9},{%0,%1,%2,%3};"
        : "+f"(c[0]), "+f"(c[1]), "+f"(c[2]), "+f"(c[3])
        : "r"(a.x), "r"(a.y), "r"(a.z), "r"(a.w), "r"(b.x), "r"(b.y));
}

// ---------------------------------------------------------------------------
// One BM=96 x BN=64 x BK=32 chunk, 256 threads (8 warps, 2x4 warp grid).
// Fragments are packed at store time:
//   sA[1536] u32: slot = ((mt*2+ks)*32 + lane)*4 + r   (16B/lane -> LDS.128)
//   sB[1024] u32: slot = ((nt*2+ks)*32 + lane)*2 + r2  ( 8B/lane -> LDS.64)
// Slot index == linear store index, so stores are sA[s]=..., conflict-free.
// A global row-major (m x k, ld=lda); B global row-major (k x n, ld=ldb).
// ---------------------------------------------------------------------------
__device__ __forceinline__ void gemm_chunk_f16(
    const float* __restrict__ Ag, int lda, int mvalid, int kvalid,
    const float* __restrict__ Bg, int ldb,
    uint32_t* sA, uint32_t* sB, float acc[3][2][4])
{
    int tid = threadIdx.x;
    __syncthreads();   // protect previous chunk's smem
    // ---- pack A (96 x 32 -> fp16 fragments) ----
#pragma unroll
    for (int t = 0; t < 6; t++) {
        int s = tid + t*256;
        int r = s & 3, lane = (s >> 2) & 31;
        int mtks = s >> 7;                 // 0..11 = mt*2+ks
        int mt = mtks >> 1, ks = mtks & 1;
        int m  = mt*16 + (lane >> 2) + ((r & 1) << 3);
        int k0 = ks*16 + ((lane & 3) << 1) + ((r >> 1) << 3);
        float v0 = (m < mvalid && k0     < kvalid) ? Ag[(size_t)m*lda + k0]   : 0.f;
        float v1 = (m < mvalid && k0 + 1 < kvalid) ? Ag[(size_t)m*lda + k0+1] : 0.f;
        __half2 h = __floats2half2_rn(v0, v1);
        sA[s] = *(uint32_t*)&h;
    }
    // ---- pack B (32 x 64 -> fp16 fragments) ----
#pragma unroll
    for (int t = 0; t < 4; t++) {
        int s = tid + t*256;
        int r2 = s & 1, lane = (s >> 1) & 31;
        int ntks = s >> 6;                 // 0..15 = nt*2+ks
        int n  = (ntks >> 1)*8 + (lane >> 2);
        int k0 = (ntks & 1)*16 + ((lane & 3) << 1) + (r2 << 3);
        float v0 = (k0     < kvalid) ? Bg[(size_t)k0*ldb + n]     : 0.f;
        float v1 = (k0 + 1 < kvalid) ? Bg[(size_t)(k0+1)*ldb + n] : 0.f;
        __half2 h = __floats2half2_rn(v0, v1);
        sB[s] = *(uint32_t*)&h;
    }
    __syncthreads();
    // ---- mma mainloop ----
    int lane = tid & 31, wid = tid >> 5;
    int wm = wid >> 2, wn = wid & 3;
#pragma unroll
    for (int ks = 0; ks < 2; ks++) {
        uint2 bf[2];
#pragma unroll
        for (int nt = 0; nt < 2; nt++) {
            int gnt = wn*2 + nt;
            bf[nt] = *(const uint2*)&sB[((gnt*2 + ks)*32 + lane)*2];
        }
#pragma unroll
        for (int mt = 0; mt < 3; mt++) {
            int gmt = wm*3 + mt;
            uint4 af = *(const uint4*)&sA[((gmt*2 + ks)*32 + lane)*4];
#pragma unroll
            for (int nt = 0; nt < 2; nt++) mma_fp16(acc[mt][nt], af, bf[nt]);
        }
    }
}

// ---------------------------------------------------------------------------
// K1: W[r,d,h] = sum_n comp[r,n] * bases[n,d,h]
// ---------------------------------------------------------------------------
__global__ void k_combine(const float* __restrict__ bases,
                          const float* __restrict__ comp) {
    int dh = blockIdx.x * blockDim.x + threadIdx.x;
    if (dh >= D_*H_) return;
    float v[NB_];
#pragma unroll
    for (int n = 0; n < NB_; n++) v[n] = bases[(size_t)n*D_*H_ + dh];
#pragma unroll
    for (int r = 0; r < R_; r++) {
        float acc = 0.f;
#pragma unroll
        for (int n = 0; n < NB_; n++) acc += __ldg(&comp[r*NB_ + n]) * v[n];
        g_W[(size_t)r*D_*H_ + dh] = acc;
    }
}

// ---------------------------------------------------------------------------
// K2: scale = M_b @ Ws^T, column softmax over t. Kept fp32 (feeds exp()).
// ---------------------------------------------------------------------------
__global__ void k_scale_softmax(const float* __restrict__ M,
                                const float* __restrict__ Ws) {
    int b = blockIdx.x;
    __shared__ float As[96][17];
    __shared__ float Bs[96][17];
    __shared__ float Cs[TT_];
    int tid = threadIdx.x;
    int ty = tid >> 4, tx = tid & 15;
    float acc[6][6] = {};
    const float* Mb = M + (size_t)b*T_*D_;

    for (int k0 = 0; k0 < D_; k0 += 16) {
        for (int i = tid; i < 96*16; i += 256) {
            int r = i >> 4, c = i & 15;
            As[r][c] = (r < T_) ? Mb[(size_t)r*D_ + k0 + c] : 0.f;
            Bs[r][c] = (r < T_) ? Ws[(size_t)r*D_ + k0 + c] : 0.f;
        }
        __syncthreads();
#pragma unroll
        for (int kk = 0; kk < 16; kk++) {
            float a[6], bb[6];
#pragma unroll
            for (int i = 0; i < 6; i++) a[i]  = As[ty*6+i][kk];
#pragma unroll
            for (int j = 0; j < 6; j++) bb[j] = Bs[tx*6+j][kk];
#pragma unroll
            for (int i = 0; i < 6; i++)
#pragma unroll
                for (int j = 0; j < 6; j++) acc[i][j] += a[i]*bb[j];
        }
        __syncthreads();
    }
#pragma unroll
    for (int i = 0; i < 6; i++) {
        int t = ty*6 + i; if (t >= T_) continue;
#pragma unroll
        for (int j = 0; j < 6; j++) {
            int s = tx*6 + j; if (s >= T_) continue;
            Cs[t*T_ + s] = acc[i][j];
        }
    }
    __syncthreads();
    if (tid < T_) {
        int s = tid;
        float mx = -1e30f;
        for (int t = 0; t < T_; t++) mx = fmaxf(mx, Cs[t*T_ + s]);
        float sum = 0.f;
        for (int t = 0; t < T_; t++) {
            float e = expf(Cs[t*T_ + s] - mx);
            Cs[t*T_ + s] = e;
            sum += e;
        }
        float inv = 1.f / sum;
        for (int t = 0; t < T_; t++)
            g_sm[(size_t)b*TT_ + t*T_ + s] = Cs[t*T_ + s] * inv;
    }
}

// ---------------------------------------------------------------------------
// K3: zero S
// ---------------------------------------------------------------------------
__global__ void k_zero_s() {
    size_t i = (size_t)blockIdx.x * blockDim.x + threadIdx.x;
    size_t stride = (size_t)gridDim.x * blockDim.x;
    for (; i < S_ELEMS; i += stride) g_S[i] = 0.f;
}

// ---------------------------------------------------------------------------
// K4: scatter edges into S
// ---------------------------------------------------------------------------
__global__ void k_scatter(const int*   __restrict__ esrc,
                          const int*   __restrict__ edst,
                          const int*   __restrict__ etype,
                          const float* __restrict__ node_att) {
    int i = blockIdx.x * blockDim.x + threadIdx.x;
    const int Eatt = B_*EA_;
    if (i < Eatt) {
        int b = i / EA_;
        int s = esrc[i], d = edst[i], r = etype[i];
        float norm = g_sm[(size_t)b*TT_ + d*T_ + s];
        atomicAdd(&g_S[(((size_t)b*R_ + r)*NPG_ + d)*T_ + s], norm);
    } else {
        int j = i - Eatt;
        if (j < B_*TO_) {
            int b   = j / TO_;
            int rem = j - b*TO_;
            int t = rem / O_, o = rem - t*O_;
            atomicAdd(&g_S[(((size_t)b*R_ + (R_-1))*NPG_ + (T_+o))*T_ + t],
                      node_att[j]);
        }
    }
}

// ---------------------------------------------------------------------------
// K5 (fp16 mma): XW[b,r] = X_b[0:T] @ W[r]
//   grid = (R*H/64 = 20, B), 256 threads, BM=96 BN=64 BK=32
// ---------------------------------------------------------------------------
__global__ void __launch_bounds__(256)
k_xw_mma(const float* __restrict__ x) {
    __shared__ __align__(16) uint32_t sA[1536];   // 6 KB
    __shared__ __align__(16) uint32_t sB[1024];   // 4 KB
    int b  = blockIdx.y;
    int n0 = blockIdx.x * 64;
    int r  = n0 / H_;
    int h0 = n0 - r*H_;
    const float* xb = x + (size_t)b*NPG_*D_;
    const float* Wr = g_W + (size_t)r*D_*H_ + h0;

    float acc[3][2][4] = {};
    for (int k0 = 0; k0 < D_; k0 += 32)
        gemm_chunk_f16(xb + k0, D_, T_, 32, Wr + (size_t)k0*H_, H_, sA, sB, acc);

    int tid = threadIdx.x, lane = tid & 31, wid = tid >> 5;
    int wm = wid >> 2, wn = wid & 3;
    float* o = g_XW + (size_t)(b*R_ + r)*T_*H_;
#pragma unroll
    for (int mt = 0; mt < 3; mt++) {
#pragma unroll
        for (int nt = 0; nt < 2; nt++) {
            int row = wm*48 + mt*16 + (lane >> 2);
            int col = h0 + wn*16 + nt*8 + ((lane & 3) << 1);
            if (row < T_)
                *(float2*)(o + (size_t)row*H_ + col) =
                    make_float2(acc[mt][nt][0], acc[mt][nt][1]);
            if (row + 8 < T_)
                *(float2*)(o + (size_t)(row+8)*H_ + col) =
                    make_float2(acc[mt][nt][2], acc[mt][nt][3]);
        }
    }
}

// ---------------------------------------------------------------------------
// K6 (fp16 mma): out[b] = sum_r S_r[b] @ XW[b,r] + x_b @ root + bias
//   grid = (H/64 = 4, B), 256 threads
// ---------------------------------------------------------------------------
__global__ void __launch_bounds__(256)
k_out_mma(const float* __restrict__ x,
          const float* __restrict__ root,
          const float* __restrict__ bias,
          float* __restrict__ out) {
    __shared__ __align__(16) uint32_t sA[1536];
    __shared__ __align__(16) uint32_t sB[1024];
    int b  = blockIdx.y;
    int h0 = blockIdx.x * 64;

    float acc[3][2][4] = {};

    // Phase 1: sum over relations; K per r = 90 in chunks of 32 (tail 26)
    for (int r = 0; r < R_; r++) {
        const float* Sb  = g_S  + (size_t)(b*R_ + r)*NPG_*T_;
        const float* XWb = g_XW + (size_t)(b*R_ + r)*T_*H_ + h0;
#pragma unroll
        for (int c = 0; c < 3; c++) {
            int s0 = c * 32;
            int kv = (T_ - s0) < 32 ? (T_ - s0) : 32;
            gemm_chunk_f16(Sb + s0, T_, NPG_, kv,
                           XWb + (size_t)s0*H_, H_, sA, sB, acc);
        }
    }
    // Phase 2: + x_b @ root
    const float* xb = x + (size_t)b*NPG_*D_;
    for (int k0 = 0; k0 < D_; k0 += 32)
        gemm_chunk_f16(xb + k0, D_, NPG_, 32,
                       root + (size_t)k0*H_ + h0, H_, sA, sB, acc);

    int tid = threadIdx.x, lane = tid & 31, wid = tid >> 5;
    int wm = wid >> 2, wn = wid & 3;
#pragma unroll
    for (int mt = 0; mt < 3; mt++) {
#pragma unroll
        for (int nt = 0; nt < 2; nt++) {
            int row = wm*48 + mt*16 + (lane >> 2);
            int col = h0 + wn*16 + nt*8 + ((lane & 3) << 1);
            if (row < NPG_) {
                float* p = out + ((size_t)b*NPG_ + row)*H_ + col;
                p[0] = acc[mt][nt][0] + bias[col];
                p[1] = acc[mt][nt][1] + bias[col+1];
            }
            if (row + 8 < NPG_) {
                float* p = out + ((size_t)b*NPG_ + row + 8)*H_ + col;
                p[0] = acc[mt][nt][2] + bias[col];
                p[1] = acc[mt][nt][3] + bias[col+1];
            }
        }
    }
}

// ---------------------------------------------------------------------------
// launch
// ---------------------------------------------------------------------------
extern "C" void kernel_launch(void* const* d_in, const int* in_sizes, int n_in,
                              void* d_out, int out_size) {
    const float* M        = (const float*)d_in[0];
    const float* x        = (const float*)d_in[1];
    const float* node_att = (const float*)d_in[2];
    const float* Ws       = (const float*)d_in[3];
    const float* bases    = (const float*)d_in[4];
    const float* comp     = (const float*)d_in[5];
    const float* root     = (const float*)d_in[6];
    const float* bias     = (const float*)d_in[7];
    const int*   esrc     = (const int*)d_in[8];
    const int*   edst     = (const int*)d_in[9];
    const int*   etype    = (const int*)d_in[10];
    float* out = (float*)d_out;

    k_combine<<<(D_*H_ + 255)/256, 256>>>(bases, comp);
    k_scale_softmax<<<B_, 256>>>(M, Ws);
    k_zero_s<<<2048, 256>>>();
    {
        int total = B_*EA_ + B_*TO_;
        k_scatter<<<(total + 255)/256, 256>>>(esrc, edst, etype, node_att);
    }
    k_xw_mma<<<dim3(R_*H_/64, B_), 256>>>(x);
    k_out_mma<<<dim3(H_/64, B_), 256>>>(x, root, bias, out);
}

// round 11
// speedup vs baseline: 2.9514x; 1.3496x over previous
#include <cuda_runtime.h>
#include <cuda_fp16.h>
#include <math.h>
#include <stdint.h>

// Problem constants
#define B_   64
#define T_   90
#define O_   5
#define D_   256
#define H_   256
#define EA_  4096
#define R_   5
#define NB_  8
#define NPG_ 95
#define TO_  (T_*O_)        // 450
#define TT_  (T_*T_)        // 8100
#define S_ELEMS ((size_t)B_*R_*NPG_*T_)

// Scratch (device globals; no allocation allowed)
__device__ float g_W [R_*D_*H_];      // combined basis weights [R,D,H]
__device__ float g_sm[B_*TT_];        // softmaxed scores
__device__ float g_S [B_*R_*NPG_*T_]; // S[b][r][dst][src], fp32 (atomics)
// fp16 fragment-layout operand buffers
__device__ __align__(16) uint32_t g_Wf[R_*4*8*1024];           // W  as B-frags [r][hb][kc][1024]
__device__ __align__(16) uint32_t g_rootf[4*8*1024];           // root as B-frags [hb][kc][1024]
__device__ __align__(16) uint32_t g_xf[(size_t)B_*8*1536];     // x  as A-frags [b][kc][1536]
__device__ __align__(16) uint32_t g_XWf[(size_t)B_*R_*4*3*1024]; // XW as B-frags [b][r][hb][c3][1024]

// ---------------------------------------------------------------------------
// helpers
// ---------------------------------------------------------------------------
__device__ __forceinline__ uint32_t smem_u32(const void* p) {
    uint32_t a;
    asm("{ .reg .u64 t; cvta.to.shared.u64 t, %1; cvt.u32.u64 %0, t; }"
        : "=r"(a) : "l"(p));
    return a;
}
#define CP16(dst, src) \
    asm volatile("cp.async.ca.shared.global [%0], [%1], 16;" :: "r"(dst), "l"(src))
#define CP_COMMIT() asm volatile("cp.async.commit_group;" ::: "memory")
#define CP_WAIT0()  asm volatile("cp.async.wait_group 0;" ::: "memory")

__device__ __forceinline__ void mma_fp16(float c[4], const uint4& a, const uint2& b) {
    asm volatile(
        "mma.sync.aligned.m16n8k16.row.col.f32.f16.f16.f32 "
        "{%0,%1,%2,%3},{%4,%5,%6,%7},{%8,%9},{%0,%1,%2,%3};"
        : "+f"(c[0]), "+f"(c[1]), "+f"(c[2]), "+f"(c[3])
        : "r"(a.x), "r"(a.y), "r"(a.z), "r"(a.w), "r"(b.x), "r"(b.y));
}

// fragment slot -> matrix coords (m16n8k16; half2 along k)
__device__ __forceinline__ void slotA(int s, int& m, int& k) {
    int r = s & 3, lane = (s >> 2) & 31, mtks = s >> 7;
    m = (mtks >> 1)*16 + (lane >> 2) + ((r & 1) << 3);
    k = (mtks & 1)*16 + ((lane & 3) << 1) + ((r >> 1) << 3);
}
__device__ __forceinline__ void slotB(int s, int& n, int& k) {
    int r2 = s & 1, lane = (s >> 1) & 31, ntks = s >> 6;
    n = (ntks >> 1)*8 + (lane >> 2);
    k = (ntks & 1)*16 + ((lane & 3) << 1) + (r2 << 3);
}

// 12 MMAs on one BM=96 x BN=64 x BK=32 fragment-packed chunk
__device__ __forceinline__ void mma_tile(const uint32_t* sA, const uint32_t* sB,
                                         float acc[3][2][4], int tid) {
    int lane = tid & 31, wid = tid >> 5;
    int wm = wid >> 2, wn = wid & 3;
#pragma unroll
    for (int ks = 0; ks < 2; ks++) {
        uint2 bf[2];
#pragma unroll
        for (int nt = 0; nt < 2; nt++)
            bf[nt] = *(const uint2*)&sB[(((wn*2+nt)*2 + ks)*32 + lane)*2];
#pragma unroll
        for (int mt = 0; mt < 3; mt++) {
            uint4 af = *(const uint4*)&sA[(((wm*3+mt)*2 + ks)*32 + lane)*4];
#pragma unroll
            for (int nt = 0; nt < 2; nt++) mma_fp16(acc[mt][nt], af, bf[nt]);
        }
    }
}

// ---------------------------------------------------------------------------
// K1: W[r,d,h] = sum_n comp[r,n] * bases[n,d,h]
// ---------------------------------------------------------------------------
__global__ void k_combine(const float* __restrict__ bases,
                          const float* __restrict__ comp) {
    int dh = blockIdx.x * blockDim.x + threadIdx.x;
    if (dh >= D_*H_) return;
    float v[NB_];
#pragma unroll
    for (int n = 0; n < NB_; n++) v[n] = bases[(size_t)n*D_*H_ + dh];
#pragma unroll
    for (int r = 0; r < R_; r++) {
        float acc = 0.f;
#pragma unroll
        for (int n = 0; n < NB_; n++) acc += __ldg(&comp[r*NB_ + n]) * v[n];
        g_W[(size_t)r*D_*H_ + dh] = acc;
    }
}

// ---------------------------------------------------------------------------
// Pre-pack kernels: build fp16 fragment-layout operand buffers
// ---------------------------------------------------------------------------
__global__ void k_pack_w() {                       // 163840 threads
    int idx = blockIdx.x * 256 + threadIdx.x;
    int r = idx >> 15, rem = idx & 32767;
    int hb = rem >> 13, kc = (rem >> 10) & 7, s = rem & 1023;
    int n, k; slotB(s, n, k);
    const float* p = g_W + (size_t)r*D_*H_ + (size_t)(kc*32 + k)*H_ + hb*64 + n;
    __half2 h = __floats2half2_rn(p[0], p[H_]);
    g_Wf[idx] = *(uint32_t*)&h;
}
__global__ void k_pack_root(const float* __restrict__ root) {  // 32768 threads
    int idx = blockIdx.x * 256 + threadIdx.x;
    int hb = idx >> 13, kc = (idx >> 10) & 7, s = idx & 1023;
    int n, k; slotB(s, n, k);
    const float* p = root + (size_t)(kc*32 + k)*H_ + hb*64 + n;
    __half2 h = __floats2half2_rn(p[0], p[H_]);
    g_rootf[idx] = *(uint32_t*)&h;
}
__global__ void k_pack_x(const float* __restrict__ x) {        // 786432 threads
    int idx = blockIdx.x * 256 + threadIdx.x;
    int b = idx / 12288;
    int rem = idx - b*12288;
    int kc = rem / 1536;
    int s  = rem - kc*1536;
    int m, k; slotA(s, m, k);
    float v0 = 0.f, v1 = 0.f;
    if (m < NPG_) {
        const float* p = x + ((size_t)b*NPG_ + m)*D_ + kc*32 + k;
        v0 = p[0]; v1 = p[1];
    }
    __half2 h = __floats2half2_rn(v0, v1);
    g_xf[idx] = *(uint32_t*)&h;
}

// ---------------------------------------------------------------------------
// K2: scale = M_b @ Ws^T, column softmax over t. Kept fp32 (feeds exp()).
// ---------------------------------------------------------------------------
__global__ void k_scale_softmax(const float* __restrict__ M,
                                const float* __restrict__ Ws) {
    int b = blockIdx.x;
    __shared__ float As[96][17];
    __shared__ float Bs[96][17];
    __shared__ float Cs[TT_];
    int tid = threadIdx.x;
    int ty = tid >> 4, tx = tid & 15;
    float acc[6][6] = {};
    const float* Mb = M + (size_t)b*T_*D_;

    for (int k0 = 0; k0 < D_; k0 += 16) {
        for (int i = tid; i < 96*16; i += 256) {
            int r = i >> 4, c = i & 15;
            As[r][c] = (r < T_) ? Mb[(size_t)r*D_ + k0 + c] : 0.f;
            Bs[r][c] = (r < T_) ? Ws[(size_t)r*D_ + k0 + c] : 0.f;
        }
        __syncthreads();
#pragma unroll
        for (int kk = 0; kk < 16; kk++) {
            float a[6], bb[6];
#pragma unroll
            for (int i = 0; i < 6; i++) a[i]  = As[ty*6+i][kk];
#pragma unroll
            for (int j = 0; j < 6; j++) bb[j] = Bs[tx*6+j][kk];
#pragma unroll
            for (int i = 0; i < 6; i++)
#pragma unroll
                for (int j = 0; j < 6; j++) acc[i][j] += a[i]*bb[j];
        }
        __syncthreads();
    }
#pragma unroll
    for (int i = 0; i < 6; i++) {
        int t = ty*6 + i; if (t >= T_) continue;
#pragma unroll
        for (int j = 0; j < 6; j++) {
            int s = tx*6 + j; if (s >= T_) continue;
            Cs[t*T_ + s] = acc[i][j];
        }
    }
    __syncthreads();
    if (tid < T_) {
        int s = tid;
        float mx = -1e30f;
        for (int t = 0; t < T_; t++) mx = fmaxf(mx, Cs[t*T_ + s]);
        float sum = 0.f;
        for (int t = 0; t < T_; t++) {
            float e = expf(Cs[t*T_ + s] - mx);
            Cs[t*T_ + s] = e;
            sum += e;
        }
        float inv = 1.f / sum;
        for (int t = 0; t < T_; t++)
            g_sm[(size_t)b*TT_ + t*T_ + s] = Cs[t*T_ + s] * inv;
    }
}

// ---------------------------------------------------------------------------
// K3/K4: zero + scatter edges into S
// ---------------------------------------------------------------------------
__global__ void k_zero_s() {
    size_t i = (size_t)blockIdx.x * blockDim.x + threadIdx.x;
    size_t stride = (size_t)gridDim.x * blockDim.x;
    for (; i < S_ELEMS; i += stride) g_S[i] = 0.f;
}
__global__ void k_scatter(const int*   __restrict__ esrc,
                          const int*   __restrict__ edst,
                          const int*   __restrict__ etype,
                          const float* __restrict__ node_att) {
    int i = blockIdx.x * blockDim.x + threadIdx.x;
    const int Eatt = B_*EA_;
    if (i < Eatt) {
        int b = i / EA_;
        int s = esrc[i], d = edst[i], r = etype[i];
        float norm = g_sm[(size_t)b*TT_ + d*T_ + s];
        atomicAdd(&g_S[(((size_t)b*R_ + r)*NPG_ + d)*T_ + s], norm);
    } else {
        int j = i - Eatt;
        if (j < B_*TO_) {
            int b   = j / TO_;
            int rem = j - b*TO_;
            int t = rem / O_, o = rem - t*O_;
            atomicAdd(&g_S[(((size_t)b*R_ + (R_-1))*NPG_ + (T_+o))*T_ + t],
                      node_att[j]);
        }
    }
}

// ---------------------------------------------------------------------------
// K5: XW frags = x_frag @ W_frag, double-buffered cp.async pipeline
//   grid (20, B): 20 = R*4 n-tiles of 64
// ---------------------------------------------------------------------------
__global__ void __launch_bounds__(256) k_xw_mma() {
    __shared__ __align__(16) uint32_t sA[2][1536];
    __shared__ __align__(16) uint32_t sB[2][1024];
    int tid = threadIdx.x;
    int b = blockIdx.y;
    int n0 = blockIdx.x * 64;
    int r  = n0 >> 8;
    int hb = (n0 & 255) >> 6;
    const uint4* Abase = (const uint4*)(g_xf + (size_t)b*8*1536);
    const uint4* Bbase = (const uint4*)(g_Wf + (size_t)((r*4 + hb)*8)*1024);

    float acc[3][2][4] = {};
    // prefetch chunk 0
    {
        uint32_t da = smem_u32(&sA[0][0]);
        CP16(da + tid*16, Abase + tid);
        if (tid < 128) CP16(da + (256+tid)*16, Abase + 256 + tid);
        uint32_t db = smem_u32(&sB[0][0]);
        CP16(db + tid*16, Bbase + tid);
        CP_COMMIT();
    }
    for (int c = 0; c < 8; c++) {
        CP_WAIT0();
        __syncthreads();
        if (c < 7) {
            int buf = (c+1) & 1;
            const uint4* As = Abase + (c+1)*384;
            uint32_t da = smem_u32(&sA[buf][0]);
            CP16(da + tid*16, As + tid);
            if (tid < 128) CP16(da + (256+tid)*16, As + 256 + tid);
            uint32_t db = smem_u32(&sB[buf][0]);
            CP16(db + tid*16, Bbase + (c+1)*256 + tid);
            CP_COMMIT();
        }
        mma_tile(sA[c & 1], sB[c & 1], acc, tid);
    }

    // Epilogue: acc -> fp16 -> smem [n][k] -> B-fragment global (g_XWf)
    __syncthreads();
    __half* sm = (__half*)&sA[0][0];          // sm[n*96 + k], 64x96 halves = 12KB
    int lane = tid & 31, wid = tid >> 5, wm = wid >> 2, wn = wid & 3;
#pragma unroll
    for (int mt = 0; mt < 3; mt++) {
#pragma unroll
        for (int nt = 0; nt < 2; nt++) {
            int row = wm*48 + mt*16 + (lane >> 2);
            int hl  = wn*16 + nt*8 + ((lane & 3) << 1);
            sm[(hl    )*96 + row    ] = __float2half(acc[mt][nt][0]);
            sm[(hl + 1)*96 + row    ] = __float2half(acc[mt][nt][1]);
            sm[(hl    )*96 + row + 8] = __float2half(acc[mt][nt][2]);
            sm[(hl + 1)*96 + row + 8] = __float2half(acc[mt][nt][3]);
        }
    }
    __syncthreads();
    const uint32_t* smu = (const uint32_t*)sm;   // smu[n*48 + k/2]
    uint32_t* dst = g_XWf + (((size_t)(b*R_ + r)*4 + hb)*3)*1024;
#pragma unroll
    for (int c3 = 0; c3 < 3; c3++) {
        uint4 v;
        uint32_t w[4];
#pragma unroll
        for (int j = 0; j < 4; j++) {
            int s = tid*4 + j;
            int n, k; slotB(s, n, k);
            k += c3*32;
            w[j] = smu[n*48 + (k >> 1)];
        }
        v.x = w[0]; v.y = w[1]; v.z = w[2]; v.w = w[3];
        *(uint4*)(dst + c3*1024 + tid*4) = v;
    }
}

// ---------------------------------------------------------------------------
// K6: out[b] = sum_r S_r @ XW_r + x @ root + bias; B operands pre-packed
//   grid (4, B); 23 chunks: 15 = 5r x 3 (K=90 over S), 8 = D/32 (root)
// ---------------------------------------------------------------------------
__global__ void __launch_bounds__(256)
k_out_mma(const float* __restrict__ bias, float* __restrict__ out) {
    __shared__ __align__(16) uint32_t sA[2][1536];
    __shared__ __align__(16) uint32_t sB[2][1024];
    int tid = threadIdx.x;
    int b = blockIdx.y;
    int h0 = blockIdx.x * 64;
    int hb = h0 >> 6;

    float acc[3][2][4] = {};
    // prefetch chunk 0 (phase 1, r=0, c3=0): B only
    {
        const uint4* Bsrc = (const uint4*)(g_XWf + (((size_t)(b*R_)*4 + hb)*3)*1024);
        uint32_t db = smem_u32(&sB[0][0]);
        CP16(db + tid*16, Bsrc + tid);
        CP_COMMIT();
    }
    for (int c = 0; c < 23; c++) {
        CP_WAIT0();
        __syncthreads();
        if (c < 22) {
            int cn = c + 1, buf = cn & 1;
            const uint4* Bsrc;
            if (cn < 15) {
                int rr = cn / 3, c3 = cn - rr*3;
                Bsrc = (const uint4*)(g_XWf + (((size_t)(b*R_ + rr)*4 + hb)*3 + c3)*1024);
            } else {
                Bsrc = (const uint4*)(g_rootf + (size_t)(hb*8 + (cn - 15))*1024);
            }
            uint32_t db = smem_u32(&sB[buf][0]);
            CP16(db + tid*16, Bsrc + tid);
            if (cn >= 15) {
                const uint4* As = (const uint4*)(g_xf + ((size_t)b*8 + (cn - 15))*1536);
                uint32_t da = smem_u32(&sA[buf][0]);
                CP16(da + tid*16, As + tid);
                if (tid < 128) CP16(da + (256+tid)*16, As + 256 + tid);
            }
            CP_COMMIT();
        }
        if (c < 15) {
            // synchronous A pack: S (fp32 -> fp16 fragments)
            int r = c / 3, s0 = (c - r*3)*32;
            int kv = (T_ - s0) < 32 ? (T_ - s0) : 32;
            const float* Sb = g_S + (size_t)(b*R_ + r)*NPG_*T_;
            uint32_t* dstA = sA[c & 1];
#pragma unroll
            for (int t = 0; t < 6; t++) {
                int s = tid + t*256;
                int m, k; slotA(s, m, k);
                float v0 = 0.f, v1 = 0.f;
                if (m < NPG_) {
                    if (k     < kv) v0 = Sb[(size_t)m*T_ + s0 + k];
                    if (k + 1 < kv) v1 = Sb[(size_t)m*T_ + s0 + k + 1];
                }
                __half2 h = __floats2half2_rn(v0, v1);
                dstA[s] = *(uint32_t*)&h;
            }
        }
        __syncthreads();
        mma_tile(sA[c & 1], sB[c & 1], acc, tid);
    }

    // Epilogue: + bias, write fp32 out
    int lane = tid & 31, wid = tid >> 5, wm = wid >> 2, wn = wid & 3;
#pragma unroll
    for (int mt = 0; mt < 3; mt++) {
#pragma unroll
        for (int nt = 0; nt < 2; nt++) {
            int row = wm*48 + mt*16 + (lane >> 2);
            int col = h0 + wn*16 + nt*8 + ((lane & 3) << 1);
            if (row < NPG_) {
                float* p = out + ((size_t)b*NPG_ + row)*H_ + col;
                p[0] = acc[mt][nt][0] + bias[col];
                p[1] = acc[mt][nt][1] + bias[col+1];
            }
            if (row + 8 < NPG_) {
                float* p = out + ((size_t)b*NPG_ + row + 8)*H_ + col;
                p[0] = acc[mt][nt][2] + bias[col];
                p[1] = acc[mt][nt][3] + bias[col+1];
            }
        }
    }
}

// ---------------------------------------------------------------------------
// launch
// ---------------------------------------------------------------------------
extern "C" void kernel_launch(void* const* d_in, const int* in_sizes, int n_in,
                              void* d_out, int out_size) {
    const float* M        = (const float*)d_in[0];
    const float* x        = (const float*)d_in[1];
    const float* node_att = (const float*)d_in[2];
    const float* Ws       = (const float*)d_in[3];
    const float* bases    = (const float*)d_in[4];
    const float* comp     = (const float*)d_in[5];
    const float* root     = (const float*)d_in[6];
    const float* bias     = (const float*)d_in[7];
    const int*   esrc     = (const int*)d_in[8];
    const int*   edst     = (const int*)d_in[9];
    const int*   etype    = (const int*)d_in[10];
    float* out = (float*)d_out;

    k_combine<<<(D_*H_ + 255)/256, 256>>>(bases, comp);
    k_pack_w<<<640, 256>>>();
    k_pack_root<<<128, 256>>>(root);
    k_pack_x<<<3072, 256>>>(x);
    k_scale_softmax<<<B_, 256>>>(M, Ws);
    k_zero_s<<<2048, 256>>>();
    {
        int total = B_*EA_ + B_*TO_;
        k_scatter<<<(total + 255)/256, 256>>>(esrc, edst, etype, node_att);
    }
    k_xw_mma<<<dim3(R_*4, B_), 256>>>();
    k_out_mma<<<dim3(H_/64, B_), 256>>>(bias, out);
}

// round 12
// speedup vs baseline: 3.0511x; 1.0338x over previous
#include <cuda_runtime.h>
#include <cuda_fp16.h>
#include <math.h>
#include <stdint.h>

// Problem constants
#define B_   64
#define T_   90
#define O_   5
#define D_   256
#define H_   256
#define EA_  4096
#define R_   5
#define NB_  8
#define NPG_ 95
#define TO_  (T_*O_)        // 450
#define TT_  (T_*T_)        // 8100
#define S_ELEMS ((size_t)B_*R_*NPG_*T_)

// Scratch (device globals; no allocation allowed)
__device__ float g_W [R_*D_*H_];      // combined basis weights [R,D,H]
__device__ float g_sm[B_*TT_];        // softmaxed scores
__device__ __align__(16) __half g_Sh[S_ELEMS]; // S[b][r][dst][src], fp16 (half atomics)
// fp16 fragment-layout operand buffers
__device__ __align__(16) uint32_t g_Wf[R_*4*8*1024];           // W  as B-frags [r][hb][kc][1024]
__device__ __align__(16) uint32_t g_rootf[4*8*1024];           // root as B-frags [hb][kc][1024]
__device__ __align__(16) uint32_t g_xf[(size_t)B_*8*1536];     // x  as A-frags [b][kc][1536]
__device__ __align__(16) uint32_t g_XWf[(size_t)B_*R_*4*3*1024]; // XW as B-frags [b][r][hb][c3][1024]

// ---------------------------------------------------------------------------
// helpers
// ---------------------------------------------------------------------------
__device__ __forceinline__ uint32_t smem_u32(const void* p) {
    uint32_t a;
    asm("{ .reg .u64 t; cvta.to.shared.u64 t, %1; cvt.u32.u64 %0, t; }"
        : "=r"(a) : "l"(p));
    return a;
}
#define CP16(dst, src) \
    asm volatile("cp.async.ca.shared.global [%0], [%1], 16;" :: "r"(dst), "l"(src))
#define CP_COMMIT() asm volatile("cp.async.commit_group;" ::: "memory")
#define CP_WAIT0()  asm volatile("cp.async.wait_group 0;" ::: "memory")

__device__ __forceinline__ void mma_fp16(float c[4], const uint4& a, const uint2& b) {
    asm volatile(
        "mma.sync.aligned.m16n8k16.row.col.f32.f16.f16.f32 "
        "{%0,%1,%2,%3},{%4,%5,%6,%7},{%8,%9},{%0,%1,%2,%3};"
        : "+f"(c[0]), "+f"(c[1]), "+f"(c[2]), "+f"(c[3])
        : "r"(a.x), "r"(a.y), "r"(a.z), "r"(a.w), "r"(b.x), "r"(b.y));
}

// fragment slot -> matrix coords (m16n8k16; half2 along k)
__device__ __forceinline__ void slotA(int s, int& m, int& k) {
    int r = s & 3, lane = (s >> 2) & 31, mtks = s >> 7;
    m = (mtks >> 1)*16 + (lane >> 2) + ((r & 1) << 3);
    k = (mtks & 1)*16 + ((lane & 3) << 1) + ((r >> 1) << 3);
}
__device__ __forceinline__ void slotB(int s, int& n, int& k) {
    int r2 = s & 1, lane = (s >> 1) & 31, ntks = s >> 6;
    n = (ntks >> 1)*8 + (lane >> 2);
    k = (ntks & 1)*16 + ((lane & 3) << 1) + (r2 << 3);
}

// 12 MMAs on one BM=96 x BN=64 x BK=32 fragment-packed chunk
__device__ __forceinline__ void mma_tile(const uint32_t* sA, const uint32_t* sB,
                                         float acc[3][2][4], int tid) {
    int lane = tid & 31, wid = tid >> 5;
    int wm = wid >> 2, wn = wid & 3;
#pragma unroll
    for (int ks = 0; ks < 2; ks++) {
        uint2 bf[2];
#pragma unroll
        for (int nt = 0; nt < 2; nt++)
            bf[nt] = *(const uint2*)&sB[(((wn*2+nt)*2 + ks)*32 + lane)*2];
#pragma unroll
        for (int mt = 0; mt < 3; mt++) {
            uint4 af = *(const uint4*)&sA[(((wm*3+mt)*2 + ks)*32 + lane)*4];
#pragma unroll
            for (int nt = 0; nt < 2; nt++) mma_fp16(acc[mt][nt], af, bf[nt]);
        }
    }
}

// ---------------------------------------------------------------------------
// K1: W[r,d,h] = sum_n comp[r,n] * bases[n,d,h]
// ---------------------------------------------------------------------------
__global__ void k_combine(const float* __restrict__ bases,
                          const float* __restrict__ comp) {
    int dh = blockIdx.x * blockDim.x + threadIdx.x;
    if (dh >= D_*H_) return;
    float v[NB_];
#pragma unroll
    for (int n = 0; n < NB_; n++) v[n] = bases[(size_t)n*D_*H_ + dh];
#pragma unroll
    for (int r = 0; r < R_; r++) {
        float acc = 0.f;
#pragma unroll
        for (int n = 0; n < NB_; n++) acc += __ldg(&comp[r*NB_ + n]) * v[n];
        g_W[(size_t)r*D_*H_ + dh] = acc;
    }
}

// ---------------------------------------------------------------------------
// Pre-pack: W (5 rels) + root as B-fragments  (768 blocks)
// ---------------------------------------------------------------------------
__global__ void k_pack_wr(const float* __restrict__ root) {
    int idx = blockIdx.x * 256 + threadIdx.x;   // < 6*32768
    int r = idx >> 15, rem = idx & 32767;
    int hb = rem >> 13, kc = (rem >> 10) & 7, s = rem & 1023;
    int n, k; slotB(s, n, k);
    const float* src = (r < R_) ? (g_W + (size_t)r*D_*H_) : root;
    const float* p = src + (size_t)(kc*32 + k)*H_ + hb*64 + n;
    __half2 h = __floats2half2_rn(p[0], p[H_]);
    if (r < R_) g_Wf[idx] = *(uint32_t*)&h;
    else        g_rootf[rem] = *(uint32_t*)&h;
}
__global__ void k_pack_x(const float* __restrict__ x) {        // 786432 threads
    int idx = blockIdx.x * 256 + threadIdx.x;
    int b = idx / 12288;
    int rem = idx - b*12288;
    int kc = rem / 1536;
    int s  = rem - kc*1536;
    int m, k; slotA(s, m, k);
    float v0 = 0.f, v1 = 0.f;
    if (m < NPG_) {
        const float* p = x + ((size_t)b*NPG_ + m)*D_ + kc*32 + k;
        v0 = p[0]; v1 = p[1];
    }
    __half2 h = __floats2half2_rn(v0, v1);
    g_xf[idx] = *(uint32_t*)&h;
}

// ---------------------------------------------------------------------------
// K2: scale = M_b @ Ws^T, column softmax over t. fp32 (feeds exp()).
//   grid (2, B): each block does 48 of 90 s-columns. 96x48 tile, 6x3/thread.
// ---------------------------------------------------------------------------
__global__ void __launch_bounds__(256)
k_scale_softmax(const float* __restrict__ M, const float* __restrict__ Ws) {
    int b  = blockIdx.y;
    int s0 = blockIdx.x * 48;
    __shared__ float As[96][17];
    __shared__ float Bs[48][17];
    __shared__ float Cs[48][97];     // [s][t], padded (97) to dodge bank conflicts
    int tid = threadIdx.x;
    int ty = tid >> 4, tx = tid & 15;
    float acc[6][3] = {};
    const float* Mb = M + (size_t)b*T_*D_;

    for (int k0 = 0; k0 < D_; k0 += 16) {
        for (int i = tid; i < 96*16; i += 256) {
            int r = i >> 4, c = i & 15;
            As[r][c] = (r < T_) ? Mb[(size_t)r*D_ + k0 + c] : 0.f;
        }
        for (int i = tid; i < 48*16; i += 256) {
            int r = i >> 4, c = i & 15;
            int sg = s0 + r;
            Bs[r][c] = (sg < T_) ? Ws[(size_t)sg*D_ + k0 + c] : 0.f;
        }
        __syncthreads();
#pragma unroll
        for (int kk = 0; kk < 16; kk++) {
            float a[6], bb[3];
#pragma unroll
            for (int i = 0; i < 6; i++) a[i]  = As[ty*6+i][kk];
#pragma unroll
            for (int j = 0; j < 3; j++) bb[j] = Bs[tx*3+j][kk];
#pragma unroll
            for (int i = 0; i < 6; i++)
#pragma unroll
                for (int j = 0; j < 3; j++) acc[i][j] += a[i]*bb[j];
        }
        __syncthreads();
    }
#pragma unroll
    for (int i = 0; i < 6; i++) {
        int t = ty*6 + i; if (t >= T_) continue;
#pragma unroll
        for (int j = 0; j < 3; j++) Cs[tx*3+j][t] = acc[i][j];
    }
    __syncthreads();
    if (tid < 48 && s0 + tid < T_) {
        int s = tid;
        float mx = -1e30f;
        for (int t = 0; t < T_; t++) mx = fmaxf(mx, Cs[s][t]);
        float sum = 0.f;
        for (int t = 0; t < T_; t++) {
            float e = expf(Cs[s][t] - mx);
            Cs[s][t] = e;
            sum += e;
        }
        float inv = 1.f / sum;
        float* dst = g_sm + (size_t)b*TT_ + (s0 + s);
        for (int t = 0; t < T_; t++) dst[t*T_] = Cs[s][t] * inv;
    }
}

// ---------------------------------------------------------------------------
// K3/K4: zero + scatter edges into S (fp16, native half atomics)
// ---------------------------------------------------------------------------
__global__ void k_zero_s() {
    size_t n16 = (S_ELEMS*2 + 15) / 16;   // uint4 count
    size_t i = (size_t)blockIdx.x * blockDim.x + threadIdx.x;
    size_t stride = (size_t)gridDim.x * blockDim.x;
    uint4 z = make_uint4(0, 0, 0, 0);
    for (; i < n16; i += stride) ((uint4*)g_Sh)[i] = z;
}
__global__ void k_scatter(const int*   __restrict__ esrc,
                          const int*   __restrict__ edst,
                          const int*   __restrict__ etype,
                          const float* __restrict__ node_att) {
    int i = blockIdx.x * blockDim.x + threadIdx.x;
    const int Eatt = B_*EA_;
    if (i < Eatt) {
        int b = i / EA_;
        int s = esrc[i], d = edst[i], r = etype[i];
        float norm = g_sm[(size_t)b*TT_ + d*T_ + s];
        atomicAdd(&g_Sh[(((size_t)b*R_ + r)*NPG_ + d)*T_ + s], __float2half(norm));
    } else {
        int j = i - Eatt;
        if (j < B_*TO_) {
            int b   = j / TO_;
            int rem = j - b*TO_;
            int t = rem / O_, o = rem - t*O_;
            atomicAdd(&g_Sh[(((size_t)b*R_ + (R_-1))*NPG_ + (T_+o))*T_ + t],
                      __float2half(node_att[j]));
        }
    }
}

// ---------------------------------------------------------------------------
// K5: XW frags = x_frag @ W_frag, double-buffered cp.async pipeline
//   grid (20, B): 20 = R*4 n-tiles of 64
// ---------------------------------------------------------------------------
__global__ void __launch_bounds__(256) k_xw_mma() {
    __shared__ __align__(16) uint32_t sA[2][1536];
    __shared__ __align__(16) uint32_t sB[2][1024];
    int tid = threadIdx.x;
    int b = blockIdx.y;
    int n0 = blockIdx.x * 64;
    int r  = n0 >> 8;
    int hb = (n0 & 255) >> 6;
    const uint4* Abase = (const uint4*)(g_xf + (size_t)b*8*1536);
    const uint4* Bbase = (const uint4*)(g_Wf + (size_t)((r*4 + hb)*8)*1024);

    float acc[3][2][4] = {};
    // prefetch chunk 0
    {
        uint32_t da = smem_u32(&sA[0][0]);
        CP16(da + tid*16, Abase + tid);
        if (tid < 128) CP16(da + (256+tid)*16, Abase + 256 + tid);
        uint32_t db = smem_u32(&sB[0][0]);
        CP16(db + tid*16, Bbase + tid);
        CP_COMMIT();
    }
    for (int c = 0; c < 8; c++) {
        CP_WAIT0();
        __syncthreads();
        if (c < 7) {
            int buf = (c+1) & 1;
            const uint4* As = Abase + (c+1)*384;
            uint32_t da = smem_u32(&sA[buf][0]);
            CP16(da + tid*16, As + tid);
            if (tid < 128) CP16(da + (256+tid)*16, As + 256 + tid);
            uint32_t db = smem_u32(&sB[buf][0]);
            CP16(db + tid*16, Bbase + (c+1)*256 + tid);
            CP_COMMIT();
        }
        mma_tile(sA[c & 1], sB[c & 1], acc, tid);
    }

    // Epilogue: acc -> fp16 -> smem [n][k] -> B-fragment global (g_XWf)
    __syncthreads();
    __half* sm = (__half*)&sA[0][0];          // sm[n*96 + k], 64x96 halves = 12KB
    int lane = tid & 31, wid = tid >> 5, wm = wid >> 2, wn = wid & 3;
#pragma unroll
    for (int mt = 0; mt < 3; mt++) {
#pragma unroll
        for (int nt = 0; nt < 2; nt++) {
            int row = wm*48 + mt*16 + (lane >> 2);
            int hl  = wn*16 + nt*8 + ((lane & 3) << 1);
            sm[(hl    )*96 + row    ] = __float2half(acc[mt][nt][0]);
            sm[(hl + 1)*96 + row    ] = __float2half(acc[mt][nt][1]);
            sm[(hl    )*96 + row + 8] = __float2half(acc[mt][nt][2]);
            sm[(hl + 1)*96 + row + 8] = __float2half(acc[mt][nt][3]);
        }
    }
    __syncthreads();
    const uint32_t* smu = (const uint32_t*)sm;   // smu[n*48 + k/2]
    uint32_t* dst = g_XWf + (((size_t)(b*R_ + r)*4 + hb)*3)*1024;
#pragma unroll
    for (int c3 = 0; c3 < 3; c3++) {
        uint4 v;
        uint32_t w[4];
#pragma unroll
        for (int j = 0; j < 4; j++) {
            int s = tid*4 + j;
            int n, k; slotB(s, n, k);
            k += c3*32;
            w[j] = smu[n*48 + (k >> 1)];
        }
        v.x = w[0]; v.y = w[1]; v.z = w[2]; v.w = w[3];
        *(uint4*)(dst + c3*1024 + tid*4) = v;
    }
}

// ---------------------------------------------------------------------------
// K6: out[b] = sum_r S_r @ XW_r + x @ root + bias; B operands pre-packed
//   grid (4, B); 23 chunks: 15 = 5r x 3 (K=90 over S), 8 = D/32 (root)
// ---------------------------------------------------------------------------
__global__ void __launch_bounds__(256)
k_out_mma(const float* __restrict__ bias, float* __restrict__ out) {
    __shared__ __align__(16) uint32_t sA[2][1536];
    __shared__ __align__(16) uint32_t sB[2][1024];
    int tid = threadIdx.x;
    int b = blockIdx.y;
    int h0 = blockIdx.x * 64;
    int hb = h0 >> 6;

    float acc[3][2][4] = {};
    // prefetch chunk 0 (phase 1, r=0, c3=0): B only
    {
        const uint4* Bsrc = (const uint4*)(g_XWf + (((size_t)(b*R_)*4 + hb)*3)*1024);
        uint32_t db = smem_u32(&sB[0][0]);
        CP16(db + tid*16, Bsrc + tid);
        CP_COMMIT();
    }
    for (int c = 0; c < 23; c++) {
        CP_WAIT0();
        __syncthreads();
        if (c < 22) {
            int cn = c + 1, buf = cn & 1;
            const uint4* Bsrc;
            if (cn < 15) {
                int rr = cn / 3, c3 = cn - rr*3;
                Bsrc = (const uint4*)(g_XWf + (((size_t)(b*R_ + rr)*4 + hb)*3 + c3)*1024);
            } else {
                Bsrc = (const uint4*)(g_rootf + (size_t)(hb*8 + (cn - 15))*1024);
            }
            uint32_t db = smem_u32(&sB[buf][0]);
            CP16(db + tid*16, Bsrc + tid);
            if (cn >= 15) {
                const uint4* As = (const uint4*)(g_xf + ((size_t)b*8 + (cn - 15))*1536);
                uint32_t da = smem_u32(&sA[buf][0]);
                CP16(da + tid*16, As + tid);
                if (tid < 128) CP16(da + (256+tid)*16, As + 256 + tid);
            }
            CP_COMMIT();
        }
        if (c < 15) {
            // synchronous A pack: S (fp16 bits -> fragments, no cvt)
            int r = c / 3, s0 = (c - r*3)*32;
            int kv = (T_ - s0) < 32 ? (T_ - s0) : 32;
            const __half* Sb = g_Sh + (size_t)(b*R_ + r)*NPG_*T_;
            uint32_t* dstA = sA[c & 1];
#pragma unroll
            for (int t = 0; t < 6; t++) {
                int s = tid + t*256;
                int m, k; slotA(s, m, k);
                uint32_t lo = 0, hi = 0;
                if (m < NPG_) {
                    const __half* p = Sb + (size_t)m*T_ + s0 + k;
                    if (k     < kv) lo = (uint32_t)__half_as_ushort(p[0]);
                    if (k + 1 < kv) hi = (uint32_t)__half_as_ushort(p[1]);
                }
                dstA[s] = lo | (hi << 16);
            }
        }
        __syncthreads();
        mma_tile(sA[c & 1], sB[c & 1], acc, tid);
    }

    // Epilogue: + bias, write fp32 out
    int lane = tid & 31, wid = tid >> 5, wm = wid >> 2, wn = wid & 3;
#pragma unroll
    for (int mt = 0; mt < 3; mt++) {
#pragma unroll
        for (int nt = 0; nt < 2; nt++) {
            int row = wm*48 + mt*16 + (lane >> 2);
            int col = h0 + wn*16 + nt*8 + ((lane & 3) << 1);
            if (row < NPG_) {
                float* p = out + ((size_t)b*NPG_ + row)*H_ + col;
                p[0] = acc[mt][nt][0] + bias[col];
                p[1] = acc[mt][nt][1] + bias[col+1];
            }
            if (row + 8 < NPG_) {
                float* p = out + ((size_t)b*NPG_ + row + 8)*H_ + col;
                p[0] = acc[mt][nt][2] + bias[col];
                p[1] = acc[mt][nt][3] + bias[col+1];
            }
        }
    }
}

// ---------------------------------------------------------------------------
// launch
// ---------------------------------------------------------------------------
extern "C" void kernel_launch(void* const* d_in, const int* in_sizes, int n_in,
                              void* d_out, int out_size) {
    const float* M        = (const float*)d_in[0];
    const float* x        = (const float*)d_in[1];
    const float* node_att = (const float*)d_in[2];
    const float* Ws       = (const float*)d_in[3];
    const float* bases    = (const float*)d_in[4];
    const float* comp     = (const float*)d_in[5];
    const float* root     = (const float*)d_in[6];
    const float* bias     = (const float*)d_in[7];
    const int*   esrc     = (const int*)d_in[8];
    const int*   edst     = (const int*)d_in[9];
    const int*   etype    = (const int*)d_in[10];
    float* out = (float*)d_out;

    k_combine<<<(D_*H_ + 255)/256, 256>>>(bases, comp);
    k_pack_wr<<<768, 256>>>(root);
    k_pack_x<<<3072, 256>>>(x);
    k_scale_softmax<<<dim3(2, B_), 256>>>(M, Ws);
    k_zero_s<<<1024, 256>>>();
    {
        int total = B_*EA_ + B_*TO_;
        k_scatter<<<(total + 255)/256, 256>>>(esrc, edst, etype, node_att);
    }
    k_xw_mma<<<dim3(R_*4, B_), 256>>>();
    k_out_mma<<<dim3(H_/64, B_), 256>>>(bias, out);
}

// round 13
// speedup vs baseline: 3.7803x; 1.2390x over previous
#include <cuda_runtime.h>
#include <cuda_fp16.h>
#include <math.h>
#include <stdint.h>

// Problem constants
#define B_   64
#define T_   90
#define O_   5
#define D_   256
#define H_   256
#define EA_  4096
#define R_   5
#define NB_  8
#define NPG_ 95
#define TO_  (T_*O_)        // 450
#define TT_  (T_*T_)        // 8100
#define S_ELEMS ((size_t)B_*R_*NPG_*T_)

// Scratch (device globals; no allocation allowed)
__device__ float g_W [R_*D_*H_];      // combined basis weights [R,D,H]
__device__ float g_smT[B_*TT_];       // softmax, TRANSPOSED: [b][s][t]
__device__ __align__(16) __half g_Sh[S_ELEMS]; // S[b][r][dst][src], fp16 (half atomics)
// fp16 fragment-layout operand buffers
__device__ __align__(16) uint32_t g_Wf[R_*4*8*1024];           // W  as B-frags [r][hb][kc][1024]
__device__ __align__(16) uint32_t g_rootf[4*8*1024];           // root as B-frags [hb][kc][1024]
__device__ __align__(16) uint32_t g_xf[(size_t)B_*8*1536];     // x  as A-frags [b][kc][1536]
__device__ __align__(16) uint32_t g_XWf[(size_t)B_*R_*4*3*1024]; // XW as B-frags [b][r][hb][c3][1024]

// ---------------------------------------------------------------------------
// helpers
// ---------------------------------------------------------------------------
__device__ __forceinline__ uint32_t smem_u32(const void* p) {
    uint32_t a;
    asm("{ .reg .u64 t; cvta.to.shared.u64 t, %1; cvt.u32.u64 %0, t; }"
        : "=r"(a) : "l"(p));
    return a;
}
#define CP16(dst, src) \
    asm volatile("cp.async.ca.shared.global [%0], [%1], 16;" :: "r"(dst), "l"(src))
#define CP_COMMIT() asm volatile("cp.async.commit_group;" ::: "memory")
#define CP_WAIT0()  asm volatile("cp.async.wait_group 0;" ::: "memory")

__device__ __forceinline__ void mma_fp16(float c[4], const uint4& a, const uint2& b) {
    asm volatile(
        "mma.sync.aligned.m16n8k16.row.col.f32.f16.f16.f32 "
        "{%0,%1,%2,%3},{%4,%5,%6,%7},{%8,%9},{%0,%1,%2,%3};"
        : "+f"(c[0]), "+f"(c[1]), "+f"(c[2]), "+f"(c[3])
        : "r"(a.x), "r"(a.y), "r"(a.z), "r"(a.w), "r"(b.x), "r"(b.y));
}

// fragment slot -> matrix coords (m16n8k16; half2 along k)
__device__ __forceinline__ void slotA(int s, int& m, int& k) {
    int r = s & 3, lane = (s >> 2) & 31, mtks = s >> 7;
    m = (mtks >> 1)*16 + (lane >> 2) + ((r & 1) << 3);
    k = (mtks & 1)*16 + ((lane & 3) << 1) + ((r >> 1) << 3);
}
__device__ __forceinline__ void slotB(int s, int& n, int& k) {
    int r2 = s & 1, lane = (s >> 1) & 31, ntks = s >> 6;
    n = (ntks >> 1)*8 + (lane >> 2);
    k = (ntks & 1)*16 + ((lane & 3) << 1) + (r2 << 3);
}

// 12 MMAs on one BM=96 x BN=64 x BK=32 fragment-packed chunk
__device__ __forceinline__ void mma_tile(const uint32_t* sA, const uint32_t* sB,
                                         float acc[3][2][4], int tid) {
    int lane = tid & 31, wid = tid >> 5;
    int wm = wid >> 2, wn = wid & 3;
#pragma unroll
    for (int ks = 0; ks < 2; ks++) {
        uint2 bf[2];
#pragma unroll
        for (int nt = 0; nt < 2; nt++)
            bf[nt] = *(const uint2*)&sB[(((wn*2+nt)*2 + ks)*32 + lane)*2];
#pragma unroll
        for (int mt = 0; mt < 3; mt++) {
            uint4 af = *(const uint4*)&sA[(((wm*3+mt)*2 + ks)*32 + lane)*4];
#pragma unroll
            for (int nt = 0; nt < 2; nt++) mma_fp16(acc[mt][nt], af, bf[nt]);
        }
    }
}

// ---------------------------------------------------------------------------
// K1: W[r,d,h] = sum_n comp[r,n] * bases[n,d,h]
// ---------------------------------------------------------------------------
__global__ void k_combine(const float* __restrict__ bases,
                          const float* __restrict__ comp) {
    int dh = blockIdx.x * blockDim.x + threadIdx.x;
    if (dh >= D_*H_) return;
    float v[NB_];
#pragma unroll
    for (int n = 0; n < NB_; n++) v[n] = bases[(size_t)n*D_*H_ + dh];
#pragma unroll
    for (int r = 0; r < R_; r++) {
        float acc = 0.f;
#pragma unroll
        for (int n = 0; n < NB_; n++) acc += __ldg(&comp[r*NB_ + n]) * v[n];
        g_W[(size_t)r*D_*H_ + dh] = acc;
    }
}

// ---------------------------------------------------------------------------
// Pre-pack: W (5 rels) + root as B-fragments  (768 blocks)
// ---------------------------------------------------------------------------
__global__ void k_pack_wr(const float* __restrict__ root) {
    int idx = blockIdx.x * 256 + threadIdx.x;   // < 6*32768
    int r = idx >> 15, rem = idx & 32767;
    int hb = rem >> 13, kc = (rem >> 10) & 7, s = rem & 1023;
    int n, k; slotB(s, n, k);
    const float* src = (r < R_) ? (g_W + (size_t)r*D_*H_) : root;
    const float* p = src + (size_t)(kc*32 + k)*H_ + hb*64 + n;
    __half2 h = __floats2half2_rn(p[0], p[H_]);
    if (r < R_) g_Wf[idx] = *(uint32_t*)&h;
    else        g_rootf[rem] = *(uint32_t*)&h;
}
__global__ void k_pack_x(const float* __restrict__ x) {        // 786432 threads
    int idx = blockIdx.x * 256 + threadIdx.x;
    int b = idx / 12288;
    int rem = idx - b*12288;
    int kc = rem / 1536;
    int s  = rem - kc*1536;
    int m, k; slotA(s, m, k);
    float v0 = 0.f, v1 = 0.f;
    if (m < NPG_) {
        const float* p = x + ((size_t)b*NPG_ + m)*D_ + kc*32 + k;
        v0 = p[0]; v1 = p[1];
    }
    __half2 h = __floats2half2_rn(v0, v1);
    g_xf[idx] = *(uint32_t*)&h;
}

// ---------------------------------------------------------------------------
// K2: scale = M_b @ Ws^T, softmax over t, store TRANSPOSED g_smT[b][s][t].
//   grid (3, B): 96x32 tile, 6x2/thread, K=256 in 16-chunks.
//   Smem is [kk][m] so inner loop is LDS.64s; warp-parallel softmax tail.
// ---------------------------------------------------------------------------
__global__ void __launch_bounds__(256)
k_scale_softmax(const float* __restrict__ M, const float* __restrict__ Ws) {
    int b  = blockIdx.y;
    int s0 = blockIdx.x * 32;
    __shared__ float As[16][98];    // [kk][m] 96 used
    __shared__ float Bs[16][34];    // [kk][s] 32 used
    __shared__ float Cs[32][100];   // [s][t]  t 0..95 (>=90 are exact 0)
    int tid = threadIdx.x;
    int ty = tid >> 4, tx = tid & 15;
    float acc[6][2] = {};
    const float* Mb = M + (size_t)b*T_*D_;

    for (int k0 = 0; k0 < D_; k0 += 16) {
        // A: 16kk x 96m (coalesced 64B global reads; conflict-free stores)
#pragma unroll
        for (int i = tid; i < 16*96; i += 256) {
            int kk = i & 15, m = i >> 4;
            As[kk][m] = (m < T_) ? Mb[(size_t)m*D_ + k0 + kk] : 0.f;
        }
        // B: 16kk x 32s
#pragma unroll
        for (int i = tid; i < 16*32; i += 256) {
            int kk = i & 15, s = i >> 4;
            int sg = s0 + s;
            Bs[kk][s] = (sg < T_) ? Ws[(size_t)sg*D_ + k0 + kk] : 0.f;
        }
        __syncthreads();
#pragma unroll
        for (int kk = 0; kk < 16; kk++) {
            float2 a0 = *(float2*)&As[kk][ty*6];
            float2 a1 = *(float2*)&As[kk][ty*6 + 2];
            float2 a2 = *(float2*)&As[kk][ty*6 + 4];
            float2 bv = *(float2*)&Bs[kk][tx*2];
            acc[0][0] += a0.x*bv.x; acc[0][1] += a0.x*bv.y;
            acc[1][0] += a0.y*bv.x; acc[1][1] += a0.y*bv.y;
            acc[2][0] += a1.x*bv.x; acc[2][1] += a1.x*bv.y;
            acc[3][0] += a1.y*bv.x; acc[3][1] += a1.y*bv.y;
            acc[4][0] += a2.x*bv.x; acc[4][1] += a2.x*bv.y;
            acc[5][0] += a2.y*bv.x; acc[5][1] += a2.y*bv.y;
        }
        __syncthreads();
    }
    // stash C[s][t]
#pragma unroll
    for (int i = 0; i < 6; i++)
#pragma unroll
        for (int j = 0; j < 2; j++)
            Cs[tx*2 + j][ty*6 + i] = acc[i][j];
    __syncthreads();

    // softmax over t (one warp per 4 columns, lanes span t)
    int wid = tid >> 5, lane = tid & 31;
#pragma unroll
    for (int q = 0; q < 4; q++) {
        int sl = wid*4 + q;
        int sg = s0 + sl;
        if (sg >= T_) continue;          // uniform across warp
        float c0 = Cs[sl][lane];
        float c1 = Cs[sl][lane + 32];
        bool  v2 = lane < (T_ - 64);     // lane < 26
        float c2 = v2 ? Cs[sl][lane + 64] : -1e30f;
        float mx = fmaxf(fmaxf(c0, c1), c2);
#pragma unroll
        for (int off = 16; off; off >>= 1)
            mx = fmaxf(mx, __shfl_xor_sync(0xFFFFFFFFu, mx, off));
        float e0 = expf(c0 - mx), e1 = expf(c1 - mx);
        float e2 = v2 ? expf(c2 - mx) : 0.f;
        float sm = e0 + e1 + e2;
#pragma unroll
        for (int off = 16; off; off >>= 1)
            sm += __shfl_xor_sync(0xFFFFFFFFu, sm, off);
        float inv = 1.f / sm;
        float* dst = g_smT + (size_t)b*TT_ + (size_t)sg*T_;
        dst[lane]      = e0 * inv;
        dst[lane + 32] = e1 * inv;
        if (v2) dst[lane + 64] = e2 * inv;
    }
}

// ---------------------------------------------------------------------------
// K3/K4: zero + scatter edges into S (fp16, native half atomics)
// ---------------------------------------------------------------------------
__global__ void k_zero_s() {
    size_t n16 = (S_ELEMS*2 + 15) / 16;   // uint4 count
    size_t i = (size_t)blockIdx.x * blockDim.x + threadIdx.x;
    size_t stride = (size_t)gridDim.x * blockDim.x;
    uint4 z = make_uint4(0, 0, 0, 0);
    for (; i < n16; i += stride) ((uint4*)g_Sh)[i] = z;
}
__global__ void k_scatter(const int*   __restrict__ esrc,
                          const int*   __restrict__ edst,
                          const int*   __restrict__ etype,
                          const float* __restrict__ node_att) {
    int i = blockIdx.x * blockDim.x + threadIdx.x;
    const int Eatt = B_*EA_;
    if (i < Eatt) {
        int b = i / EA_;
        int s = esrc[i], d = edst[i], r = etype[i];
        float norm = g_smT[(size_t)b*TT_ + (size_t)s*T_ + d];
        atomicAdd(&g_Sh[(((size_t)b*R_ + r)*NPG_ + d)*T_ + s], __float2half(norm));
    } else {
        int j = i - Eatt;
        if (j < B_*TO_) {
            int b   = j / TO_;
            int rem = j - b*TO_;
            int t = rem / O_, o = rem - t*O_;
            atomicAdd(&g_Sh[(((size_t)b*R_ + (R_-1))*NPG_ + (T_+o))*T_ + t],
                      __float2half(node_att[j]));
        }
    }
}

// ---------------------------------------------------------------------------
// K5: XW frags = x_frag @ W_frag, double-buffered cp.async pipeline
//   grid (20, B): 20 = R*4 n-tiles of 64
// ---------------------------------------------------------------------------
__global__ void __launch_bounds__(256) k_xw_mma() {
    __shared__ __align__(16) uint32_t sA[2][1536];
    __shared__ __align__(16) uint32_t sB[2][1024];
    int tid = threadIdx.x;
    int b = blockIdx.y;
    int n0 = blockIdx.x * 64;
    int r  = n0 >> 8;
    int hb = (n0 & 255) >> 6;
    const uint4* Abase = (const uint4*)(g_xf + (size_t)b*8*1536);
    const uint4* Bbase = (const uint4*)(g_Wf + (size_t)((r*4 + hb)*8)*1024);

    float acc[3][2][4] = {};
    // prefetch chunk 0
    {
        uint32_t da = smem_u32(&sA[0][0]);
        CP16(da + tid*16, Abase + tid);
        if (tid < 128) CP16(da + (256+tid)*16, Abase + 256 + tid);
        uint32_t db = smem_u32(&sB[0][0]);
        CP16(db + tid*16, Bbase + tid);
        CP_COMMIT();
    }
    for (int c = 0; c < 8; c++) {
        CP_WAIT0();
        __syncthreads();
        if (c < 7) {
            int buf = (c+1) & 1;
            const uint4* As = Abase + (c+1)*384;
            uint32_t da = smem_u32(&sA[buf][0]);
            CP16(da + tid*16, As + tid);
            if (tid < 128) CP16(da + (256+tid)*16, As + 256 + tid);
            uint32_t db = smem_u32(&sB[buf][0]);
            CP16(db + tid*16, Bbase + (c+1)*256 + tid);
            CP_COMMIT();
        }
        mma_tile(sA[c & 1], sB[c & 1], acc, tid);
    }

    // Epilogue: acc -> fp16 -> smem [n][k] -> B-fragment global (g_XWf)
    __syncthreads();
    __half* sm = (__half*)&sA[0][0];          // sm[n*96 + k], 64x96 halves = 12KB
    int lane = tid & 31, wid = tid >> 5, wm = wid >> 2, wn = wid & 3;
#pragma unroll
    for (int mt = 0; mt < 3; mt++) {
#pragma unroll
        for (int nt = 0; nt < 2; nt++) {
            int row = wm*48 + mt*16 + (lane >> 2);
            int hl  = wn*16 + nt*8 + ((lane & 3) << 1);
            sm[(hl    )*96 + row    ] = __float2half(acc[mt][nt][0]);
            sm[(hl + 1)*96 + row    ] = __float2half(acc[mt][nt][1]);
            sm[(hl    )*96 + row + 8] = __float2half(acc[mt][nt][2]);
            sm[(hl + 1)*96 + row + 8] = __float2half(acc[mt][nt][3]);
        }
    }
    __syncthreads();
    const uint32_t* smu = (const uint32_t*)sm;   // smu[n*48 + k/2]
    uint32_t* dst = g_XWf + (((size_t)(b*R_ + r)*4 + hb)*3)*1024;
#pragma unroll
    for (int c3 = 0; c3 < 3; c3++) {
        uint4 v;
        uint32_t w[4];
#pragma unroll
        for (int j = 0; j < 4; j++) {
            int s = tid*4 + j;
            int n, k; slotB(s, n, k);
            k += c3*32;
            w[j] = smu[n*48 + (k >> 1)];
        }
        v.x = w[0]; v.y = w[1]; v.z = w[2]; v.w = w[3];
        *(uint4*)(dst + c3*1024 + tid*4) = v;
    }
}

// ---------------------------------------------------------------------------
// K6: out[b] = sum_r S_r @ XW_r + x @ root + bias; B operands pre-packed
//   grid (4, B); 23 chunks: 15 = 5r x 3 (K=90 over S), 8 = D/32 (root)
// ---------------------------------------------------------------------------
__global__ void __launch_bounds__(256)
k_out_mma(const float* __restrict__ bias, float* __restrict__ out) {
    __shared__ __align__(16) uint32_t sA[2][1536];
    __shared__ __align__(16) uint32_t sB[2][1024];
    int tid = threadIdx.x;
    int b = blockIdx.y;
    int h0 = blockIdx.x * 64;
    int hb = h0 >> 6;

    float acc[3][2][4] = {};
    // prefetch chunk 0 (phase 1, r=0, c3=0): B only
    {
        const uint4* Bsrc = (const uint4*)(g_XWf + (((size_t)(b*R_)*4 + hb)*3)*1024);
        uint32_t db = smem_u32(&sB[0][0]);
        CP16(db + tid*16, Bsrc + tid);
        CP_COMMIT();
    }
    for (int c = 0; c < 23; c++) {
        CP_WAIT0();
        __syncthreads();
        if (c < 22) {
            int cn = c + 1, buf = cn & 1;
            const uint4* Bsrc;
            if (cn < 15) {
                int rr = cn / 3, c3 = cn - rr*3;
                Bsrc = (const uint4*)(g_XWf + (((size_t)(b*R_ + rr)*4 + hb)*3 + c3)*1024);
            } else {
                Bsrc = (const uint4*)(g_rootf + (size_t)(hb*8 + (cn - 15))*1024);
            }
            uint32_t db = smem_u32(&sB[buf][0]);
            CP16(db + tid*16, Bsrc + tid);
            if (cn >= 15) {
                const uint4* As = (const uint4*)(g_xf + ((size_t)b*8 + (cn - 15))*1536);
                uint32_t da = smem_u32(&sA[buf][0]);
                CP16(da + tid*16, As + tid);
                if (tid < 128) CP16(da + (256+tid)*16, As + 256 + tid);
            }
            CP_COMMIT();
        }
        if (c < 15) {
            // synchronous A pack: S (fp16 bits -> fragments, no cvt)
            int r = c / 3, s0 = (c - r*3)*32;
            int kv = (T_ - s0) < 32 ? (T_ - s0) : 32;
            const __half* Sb = g_Sh + (size_t)(b*R_ + r)*NPG_*T_;
            uint32_t* dstA = sA[c & 1];
#pragma unroll
            for (int t = 0; t < 6; t++) {
                int s = tid + t*256;
                int m, k; slotA(s, m, k);
                uint32_t lo = 0, hi = 0;
                if (m < NPG_) {
                    const __half* p = Sb + (size_t)m*T_ + s0 + k;
                    if (k     < kv) lo = (uint32_t)__half_as_ushort(p[0]);
                    if (k + 1 < kv) hi = (uint32_t)__half_as_ushort(p[1]);
                }
                dstA[s] = lo | (hi << 16);
            }
        }
        __syncthreads();
        mma_tile(sA[c & 1], sB[c & 1], acc, tid);
    }

    // Epilogue: + bias, write fp32 out
    int lane = tid & 31, wid = tid >> 5, wm = wid >> 2, wn = wid & 3;
#pragma unroll
    for (int mt = 0; mt < 3; mt++) {
#pragma unroll
        for (int nt = 0; nt < 2; nt++) {
            int row = wm*48 + mt*16 + (lane >> 2);
            int col = h0 + wn*16 + nt*8 + ((lane & 3) << 1);
            if (row < NPG_) {
                float* p = out + ((size_t)b*NPG_ + row)*H_ + col;
                p[0] = acc[mt][nt][0] + bias[col];
                p[1] = acc[mt][nt][1] + bias[col+1];
            }
            if (row + 8 < NPG_) {
                float* p = out + ((size_t)b*NPG_ + row + 8)*H_ + col;
                p[0] = acc[mt][nt][2] + bias[col];
                p[1] = acc[mt][nt][3] + bias[col+1];
            }
        }
    }
}

// ---------------------------------------------------------------------------
// launch
// ---------------------------------------------------------------------------
extern "C" void kernel_launch(void* const* d_in, const int* in_sizes, int n_in,
                              void* d_out, int out_size) {
    const float* M        = (const float*)d_in[0];
    const float* x        = (const float*)d_in[1];
    const float* node_att = (const float*)d_in[2];
    const float* Ws       = (const float*)d_in[3];
    const float* bases    = (const float*)d_in[4];
    const float* comp     = (const float*)d_in[5];
    const float* root     = (const float*)d_in[6];
    const float* bias     = (const float*)d_in[7];
    const int*   esrc     = (const int*)d_in[8];
    const int*   edst     = (const int*)d_in[9];
    const int*   etype    = (const int*)d_in[10];
    float* out = (float*)d_out;

    k_combine<<<(D_*H_ + 255)/256, 256>>>(bases, comp);
    k_pack_wr<<<768, 256>>>(root);
    k_pack_x<<<3072, 256>>>(x);
    k_scale_softmax<<<dim3(3, B_), 256>>>(M, Ws);
    k_zero_s<<<1024, 256>>>();
    {
        int total = B_*EA_ + B_*TO_;
        k_scatter<<<(total + 255)/256, 256>>>(esrc, edst, etype, node_att);
    }
    k_xw_mma<<<dim3(R_*4, B_), 256>>>();
    k_out_mma<<<dim3(H_/64, B_), 256>>>(bias, out);
}